// round 1
// baseline (speedup 1.0000x reference)
#include <cuda_runtime.h>

#define H_    16
#define DM    1024
#define DK    64
#define BATCH 2
#define SEQ   2048
#define NROW  (BATCH*SEQ)   // 4096
#define NREL  65
#define SMPAD 68

// Scratch (device globals: allocation-free scratch per harness rules)
__device__ float g_q[(size_t)BATCH*H_*SEQ*DK];
__device__ float g_k[(size_t)BATCH*H_*SEQ*DK];
__device__ float g_v[(size_t)BATCH*H_*SEQ*DK];
__device__ float g_att[(size_t)NROW*DM];
__device__ float g_rb[NREL];

// ---------------------------------------------------------------------------
// rel bias: rb[i] = sum_d rel_emb[i][d]
// ---------------------------------------------------------------------------
__global__ void relbias_kernel(const float* __restrict__ rel_emb) {
    int i = threadIdx.x;
    if (i < NREL) {
        float s = 0.f;
        #pragma unroll
        for (int d = 0; d < DK; d++) s += rel_emb[i*DK + d];
        g_rb[i] = s;
    }
}

// ---------------------------------------------------------------------------
// Y = X @ W^T + bias.  M=NROW, N=DM, K=DM.
// mode 0/1/2: X=Xin, scatter Y into g_q/g_k/g_v as [b,h,s,dk]
// mode 3:     X=g_att, Y plain row-major into Yout
// 64x64 block tile, BK=16, 256 threads, 4x4 per-thread micro-tile.
// ---------------------------------------------------------------------------
__global__ void __launch_bounds__(256) gemm_bias_kernel(
    const float* __restrict__ Xin, const float* __restrict__ W,
    const float* __restrict__ bias, float* __restrict__ Yout, int mode)
{
    __shared__ float As[16][SMPAD];
    __shared__ float Bs[16][SMPAD];
    const float* X = (mode == 3) ? g_att : Xin;

    int tid = threadIdx.x;
    int tx = tid & 15, ty = tid >> 4;
    int n0 = blockIdx.x << 6;
    int m0 = blockIdx.y << 6;
    int lr = tid >> 2;           // 0..63
    int lc = (tid & 3) << 2;     // 0,4,8,12

    float acc[4][4] = {};
    const float* xp = X + (size_t)(m0 + lr) * DM + lc;
    const float* wp = W + (size_t)(n0 + lr) * DM + lc;

    for (int k0 = 0; k0 < DM; k0 += 16) {
        float4 xa = *(const float4*)(xp + k0);
        float4 wa = *(const float4*)(wp + k0);
        As[lc+0][lr] = xa.x; As[lc+1][lr] = xa.y; As[lc+2][lr] = xa.z; As[lc+3][lr] = xa.w;
        Bs[lc+0][lr] = wa.x; Bs[lc+1][lr] = wa.y; Bs[lc+2][lr] = wa.z; Bs[lc+3][lr] = wa.w;
        __syncthreads();
        #pragma unroll
        for (int kk = 0; kk < 16; kk++) {
            float4 a = *(const float4*)&As[kk][ty << 2];
            float4 b = *(const float4*)&Bs[kk][tx << 2];
            acc[0][0] += a.x*b.x; acc[0][1] += a.x*b.y; acc[0][2] += a.x*b.z; acc[0][3] += a.x*b.w;
            acc[1][0] += a.y*b.x; acc[1][1] += a.y*b.y; acc[1][2] += a.y*b.z; acc[1][3] += a.y*b.w;
            acc[2][0] += a.z*b.x; acc[2][1] += a.z*b.y; acc[2][2] += a.z*b.z; acc[2][3] += a.z*b.w;
            acc[3][0] += a.w*b.x; acc[3][1] += a.w*b.y; acc[3][2] += a.w*b.z; acc[3][3] += a.w*b.w;
        }
        __syncthreads();
    }

    #pragma unroll
    for (int j = 0; j < 4; j++) {
        int n = n0 + (tx << 2) + j;
        float bv = bias[n];
        #pragma unroll
        for (int i = 0; i < 4; i++) {
            int m = m0 + (ty << 2) + i;
            float y = acc[i][j] + bv;
            if (mode < 3) {
                float* dst = (mode == 0) ? g_q : (mode == 1) ? g_k : g_v;
                int b  = m >> 11;          // / SEQ
                int s  = m & (SEQ - 1);
                int h  = n >> 6;           // / DK
                int dk = n & 63;
                dst[(((size_t)b*H_ + h)*SEQ + s)*DK + dk] = y;
            } else {
                Yout[(size_t)m*DM + n] = y;
            }
        }
    }
}

// ---------------------------------------------------------------------------
// Flash attention per (b,h): BQ=BK=64, streaming softmax.
// Smem: Qt[d][q], KP[.][.] (K^T in phase 1, P^T [k][q] in phase 2), Vs[k][d].
// 256 threads, 4x4 micro-tiles for both GEMMs.
// ---------------------------------------------------------------------------
__global__ void __launch_bounds__(256) attn_kernel(const int* __restrict__ mask)
{
    extern __shared__ float sm[];
    float* Qt     = sm;                   // [64][SMPAD]
    float* KP     = Qt + 64*SMPAD;        // [64][SMPAD]
    float* Vs     = KP + 64*SMPAD;        // [64][SMPAD]
    float* s_rb   = Vs + 64*SMPAD;        // 65 (+3 pad)
    float* s_m    = s_rb + 68;            // 64
    float* s_l    = s_m + 64;             // 64
    float* s_f    = s_l + 64;             // 64
    float* s_part = s_f + 64;             // [4][64]

    int tid = threadIdx.x;
    int tx = tid & 15, ty = tid >> 4;
    int bh = blockIdx.y;
    int b  = bh >> 4;                     // / H_
    int h  = bh & 15;
    int q0 = blockIdx.x << 6;

    if (tid < NREL) s_rb[tid] = g_rb[tid];
    if (tid < 64) { s_m[tid] = -1e30f; s_l[tid] = 0.f; }

    // load Q tile transposed: Qt[d][q]
    {
        const float* qp = g_q + ((size_t)bh*SEQ + q0)*DK;
        int d0 = (tid & 15) << 2;
        #pragma unroll
        for (int r = 0; r < 4; r++) {
            int qi = (tid >> 4) + (r << 4);
            float4 v = *(const float4*)&qp[qi*DK + d0];
            Qt[(d0+0)*SMPAD + qi] = v.x;
            Qt[(d0+1)*SMPAD + qi] = v.y;
            Qt[(d0+2)*SMPAD + qi] = v.z;
            Qt[(d0+3)*SMPAD + qi] = v.w;
        }
    }

    float o[4][4] = {};
    const float* kbase = g_k + (size_t)bh*SEQ*DK;
    const float* vbase = g_v + (size_t)bh*SEQ*DK;
    const int*   mbase = mask + ((size_t)b*SEQ + q0)*SEQ;

    for (int kt = 0; kt < SEQ/64; kt++) {
        int k0 = kt << 6;
        __syncthreads();  // previous-tile PV done (and Q/init done on first iter)

        // load K transposed (KP[d][k]) and V natural (Vs[k][d])
        {
            int d0 = (tid & 15) << 2;
            #pragma unroll
            for (int r = 0; r < 4; r++) {
                int kj = (tid >> 4) + (r << 4);
                float4 kv = *(const float4*)&kbase[(size_t)(k0+kj)*DK + d0];
                KP[(d0+0)*SMPAD + kj] = kv.x;
                KP[(d0+1)*SMPAD + kj] = kv.y;
                KP[(d0+2)*SMPAD + kj] = kv.z;
                KP[(d0+3)*SMPAD + kj] = kv.w;
                float4 vv = *(const float4*)&vbase[(size_t)(k0+kj)*DK + d0];
                *(float4*)&Vs[kj*SMPAD + d0] = vv;
            }
        }
        __syncthreads();

        // S = Q @ K^T   (4x4 per thread)
        float sacc[4][4] = {};
        #pragma unroll 8
        for (int d = 0; d < 64; d++) {
            float4 a = *(const float4*)&Qt[d*SMPAD + (ty << 2)];
            float4 c = *(const float4*)&KP[d*SMPAD + (tx << 2)];
            sacc[0][0] += a.x*c.x; sacc[0][1] += a.x*c.y; sacc[0][2] += a.x*c.z; sacc[0][3] += a.x*c.w;
            sacc[1][0] += a.y*c.x; sacc[1][1] += a.y*c.y; sacc[1][2] += a.y*c.z; sacc[1][3] += a.y*c.w;
            sacc[2][0] += a.z*c.x; sacc[2][1] += a.z*c.y; sacc[2][2] += a.z*c.z; sacc[2][3] += a.z*c.w;
            sacc[3][0] += a.w*c.x; sacc[3][1] += a.w*c.y; sacc[3][2] += a.w*c.z; sacc[3][3] += a.w*c.w;
        }
        __syncthreads();  // done reading K; KP reusable

        // scale + rel bias + mask; store transposed as KP[k][q]
        #pragma unroll
        for (int i = 0; i < 4; i++) {
            int q = q0 + (ty << 2) + i;
            const int* mrow = mbase + (size_t)((ty << 2) + i)*SEQ + k0;
            #pragma unroll
            for (int j = 0; j < 4; j++) {
                int kc = (tx << 2) + j;
                int k  = k0 + kc;
                int rel = q - k;
                rel = min(max(rel, -32), 32) + 32;
                float s = sacc[i][j]*0.125f + s_rb[rel];
                if (mrow[kc] == 0) s = -1e9f;
                KP[kc*SMPAD + (ty << 2) + i] = s;
            }
        }
        __syncthreads();

        // streaming softmax over this tile
        int q   = tid & 63;
        int seg = tid >> 6;
        float mx = -1e30f;
        #pragma unroll
        for (int kk = 0; kk < 16; kk++)
            mx = fmaxf(mx, KP[(seg*16 + kk)*SMPAD + q]);
        s_part[seg*64 + q] = mx;
        __syncthreads();
        if (tid < 64) {
            float mt = fmaxf(fmaxf(s_part[tid], s_part[64+tid]),
                             fmaxf(s_part[128+tid], s_part[192+tid]));
            float mnew = fmaxf(s_m[tid], mt);
            s_f[tid] = __expf(s_m[tid] - mnew);
            s_m[tid] = mnew;
        }
        __syncthreads();
        float msh = s_m[q];
        float psum = 0.f;
        #pragma unroll
        for (int kk = 0; kk < 16; kk++) {
            int idx = (seg*16 + kk)*SMPAD + q;
            float p = __expf(KP[idx] - msh);
            KP[idx] = p;
            psum += p;
        }
        s_part[seg*64 + q] = psum;
        // rescale running O by f (s_f valid since sync above)
        #pragma unroll
        for (int i = 0; i < 4; i++) {
            float fr = s_f[(ty << 2) + i];
            #pragma unroll
            for (int j = 0; j < 4; j++) o[i][j] *= fr;
        }
        __syncthreads();
        if (tid < 64)
            s_l[tid] = s_l[tid]*s_f[tid]
                     + s_part[tid] + s_part[64+tid] + s_part[128+tid] + s_part[192+tid];

        // O += P @ V
        #pragma unroll 8
        for (int kk = 0; kk < 64; kk++) {
            float4 p4 = *(const float4*)&KP[kk*SMPAD + (ty << 2)];
            float4 v4 = *(const float4*)&Vs[kk*SMPAD + (tx << 2)];
            o[0][0] += p4.x*v4.x; o[0][1] += p4.x*v4.y; o[0][2] += p4.x*v4.z; o[0][3] += p4.x*v4.w;
            o[1][0] += p4.y*v4.x; o[1][1] += p4.y*v4.y; o[1][2] += p4.y*v4.z; o[1][3] += p4.y*v4.w;
            o[2][0] += p4.z*v4.x; o[2][1] += p4.z*v4.y; o[2][2] += p4.z*v4.z; o[2][3] += p4.z*v4.w;
            o[3][0] += p4.w*v4.x; o[3][1] += p4.w*v4.y; o[3][2] += p4.w*v4.z; o[3][3] += p4.w*v4.w;
        }
    }
    __syncthreads();

    // normalize + write to g_att[b*SEQ+q][h*DK + d]
    #pragma unroll
    for (int i = 0; i < 4; i++) {
        int q = q0 + (ty << 2) + i;
        float inv = 1.f / s_l[(ty << 2) + i];
        float4 r;
        r.x = o[i][0]*inv; r.y = o[i][1]*inv; r.z = o[i][2]*inv; r.w = o[i][3]*inv;
        *(float4*)&g_att[((size_t)b*SEQ + q)*DM + h*DK + (tx << 2)] = r;
    }
}

// ---------------------------------------------------------------------------
extern "C" void kernel_launch(void* const* d_in, const int* in_sizes, int n_in,
                              void* d_out, int out_size)
{
    const float* query = (const float*)d_in[0];
    const float* key   = (const float*)d_in[1];
    const float* value = (const float*)d_in[2];
    const int*   mask  = (const int*)  d_in[3];
    const float* Wq    = (const float*)d_in[4];
    const float* bq    = (const float*)d_in[5];
    const float* Wk    = (const float*)d_in[6];
    const float* bk    = (const float*)d_in[7];
    const float* Wv    = (const float*)d_in[8];
    const float* bv    = (const float*)d_in[9];
    const float* Wo    = (const float*)d_in[10];
    const float* bo    = (const float*)d_in[11];
    const float* rel   = (const float*)d_in[12];
    float* out = (float*)d_out;

    static int smem_set = 0;
    (void)smem_set; // idempotent attribute set (capturable; not a stream op)
    cudaFuncSetAttribute(attn_kernel, cudaFuncAttributeMaxDynamicSharedMemorySize, 56*1024);

    relbias_kernel<<<1, 128>>>(rel);

    dim3 pg(DM/64, NROW/64);
    gemm_bias_kernel<<<pg, 256>>>(query, Wq, bq, nullptr, 0);
    gemm_bias_kernel<<<pg, 256>>>(key,   Wk, bk, nullptr, 1);
    gemm_bias_kernel<<<pg, 256>>>(value, Wv, bv, nullptr, 2);

    size_t smem = (size_t)(3*64*SMPAD + 68 + 3*64 + 256) * sizeof(float);
    attn_kernel<<<dim3(SEQ/64, BATCH*H_), 256, smem>>>(mask);

    gemm_bias_kernel<<<pg, 256>>>(nullptr, Wo, bo, out, 3);
}

// round 2
// speedup vs baseline: 2.1165x; 2.1165x over previous
#include <cuda_runtime.h>

#define H_    16
#define DM    1024
#define DK    64
#define BATCH 2
#define SEQ   2048
#define NROW  (BATCH*SEQ)   // 4096
#define NREL  65
#define LOG2E 1.4426950408889634f
#define SCALE_L2 (0.125f*LOG2E)

// Scratch (device globals: allocation-free scratch per harness rules)
__device__ float g_q[(size_t)BATCH*H_*SEQ*DK];
__device__ float g_k[(size_t)BATCH*H_*SEQ*DK];
__device__ float g_v[(size_t)BATCH*H_*SEQ*DK];
__device__ float g_att[(size_t)NROW*DM];
__device__ float g_rb[NREL];

// ---------------------------------------------------------------------------
// helpers
// ---------------------------------------------------------------------------
__device__ __forceinline__ unsigned f2tf(float x){
    unsigned r; asm("cvt.rna.tf32.f32 %0, %1;" : "=r"(r) : "f"(x)); return r;
}
__device__ __forceinline__ void mma8(float d[4],
    unsigned a0,unsigned a1,unsigned a2,unsigned a3, unsigned b0,unsigned b1){
    asm volatile("mma.sync.aligned.m16n8k8.row.col.f32.tf32.tf32.f32 "
        "{%0,%1,%2,%3}, {%4,%5,%6,%7}, {%8,%9}, {%0,%1,%2,%3};"
        : "+f"(d[0]),"+f"(d[1]),"+f"(d[2]),"+f"(d[3])
        : "r"(a0),"r"(a1),"r"(a2),"r"(a3),"r"(b0),"r"(b1));
}
// exp2 on the fma/alu pipes (MUFU is only 0.5/cyc/SM on sm_103a)
__device__ __forceinline__ float fexp2(float y){
    y = fmaxf(y, -126.f);
    float z = y + 12582912.f;               // 2^23+2^22 round-to-int trick
    int   e = __float_as_int(z) - 0x4B400000;
    float f = y - (z - 12582912.f);         // in [-0.5, 0.5]
    float p =             1.3333558146e-3f;
    p = fmaf(p, f, 9.6181291918e-3f);
    p = fmaf(p, f, 5.5504108664e-2f);
    p = fmaf(p, f, 2.4022650695e-1f);
    p = fmaf(p, f, 6.9314718056e-1f);
    p = fmaf(p, f, 1.0f);
    return __int_as_float(__float_as_int(p) + (e << 23));
}

// ---------------------------------------------------------------------------
// rel bias (pre-scaled into log2 domain): rb[i] = LOG2E * sum_d rel_emb[i][d]
// ---------------------------------------------------------------------------
__global__ void relbias_kernel(const float* __restrict__ rel_emb) {
    int i = threadIdx.x;
    if (i < NREL) {
        float s = 0.f;
        #pragma unroll
        for (int d = 0; d < DK; d++) s += rel_emb[i*DK + d];
        g_rb[i] = s * LOG2E;
    }
}

// ---------------------------------------------------------------------------
// Y = X @ W^T + bias via tf32 mma.sync.  M=NROW, N=DM, K=DM.
// BM=128, BN=64, BK=32, 256 threads, warps 4(m)x2(n), warp tile 32x32.
// mode 0/1/2: scatter into g_q/g_k/g_v [b,h,s,dk]; mode 3: row-major Yout.
// ---------------------------------------------------------------------------
#define GBM 128
#define GBN 64
#define GBK 32
#define GPAD 36

__global__ void __launch_bounds__(256) gemm_tf32_kernel(
    const float* __restrict__ Xin, const float* __restrict__ W,
    const float* __restrict__ bias, float* __restrict__ Yout, int mode)
{
    __shared__ unsigned As[GBM][GPAD];
    __shared__ unsigned Bs[GBN][GPAD];
    const float* X = (mode == 3) ? g_att : Xin;

    int tid  = threadIdx.x;
    int lane = tid & 31, w = tid >> 5;
    int gid  = lane >> 2, tig = lane & 3;
    int wm   = w >> 1,    wn  = w & 1;
    int m0   = blockIdx.y * GBM, n0 = blockIdx.x * GBN;

    float acc[2][4][4] = {};

    for (int k0 = 0; k0 < DM; k0 += GBK) {
        #pragma unroll
        for (int i = 0; i < 4; i++) {
            int idx = tid + i*256, r = idx >> 3, c = (idx & 7) * 4;
            float4 v = *(const float4*)&X[(size_t)(m0 + r)*DM + k0 + c];
            uint4 u; u.x=f2tf(v.x); u.y=f2tf(v.y); u.z=f2tf(v.z); u.w=f2tf(v.w);
            *(uint4*)&As[r][c] = u;
        }
        #pragma unroll
        for (int i = 0; i < 2; i++) {
            int idx = tid + i*256, r = idx >> 3, c = (idx & 7) * 4;
            float4 v = *(const float4*)&W[(size_t)(n0 + r)*DM + k0 + c];
            uint4 u; u.x=f2tf(v.x); u.y=f2tf(v.y); u.z=f2tf(v.z); u.w=f2tf(v.w);
            *(uint4*)&Bs[r][c] = u;
        }
        __syncthreads();
        #pragma unroll
        for (int kk = 0; kk < 4; kk++) {
            int kc = kk * 8;
            unsigned a[2][4], b[4][2];
            #pragma unroll
            for (int mi = 0; mi < 2; mi++) {
                int r = wm*32 + mi*16 + gid;
                a[mi][0] = As[r  ][kc + tig];
                a[mi][1] = As[r+8][kc + tig];
                a[mi][2] = As[r  ][kc + tig + 4];
                a[mi][3] = As[r+8][kc + tig + 4];
            }
            #pragma unroll
            for (int ni = 0; ni < 4; ni++) {
                int r = wn*32 + ni*8 + gid;
                b[ni][0] = Bs[r][kc + tig];
                b[ni][1] = Bs[r][kc + tig + 4];
            }
            #pragma unroll
            for (int mi = 0; mi < 2; mi++)
                #pragma unroll
                for (int ni = 0; ni < 4; ni++)
                    mma8(acc[mi][ni], a[mi][0],a[mi][1],a[mi][2],a[mi][3],
                         b[ni][0], b[ni][1]);
        }
        __syncthreads();
    }

    #pragma unroll
    for (int mi = 0; mi < 2; mi++) {
        #pragma unroll
        for (int ni = 0; ni < 4; ni++) {
            int row = m0 + wm*32 + mi*16 + gid;
            int col = n0 + wn*32 + ni*8 + 2*tig;
            float bv0 = bias[col], bv1 = bias[col+1];
            float2 v01 = make_float2(acc[mi][ni][0] + bv0, acc[mi][ni][1] + bv1);
            float2 v23 = make_float2(acc[mi][ni][2] + bv0, acc[mi][ni][3] + bv1);
            if (mode < 3) {
                float* dst = (mode == 0) ? g_q : (mode == 1) ? g_k : g_v;
                int hh = col >> 6, dk = col & 63;
                {
                    int b = row >> 11, s = row & (SEQ-1);
                    *(float2*)&dst[(((size_t)b*H_ + hh)*SEQ + s)*DK + dk] = v01;
                }
                {
                    int r2 = row + 8;
                    int b = r2 >> 11, s = r2 & (SEQ-1);
                    *(float2*)&dst[(((size_t)b*H_ + hh)*SEQ + s)*DK + dk] = v23;
                }
            } else {
                *(float2*)&Yout[(size_t)row*DM + col]     = v01;
                *(float2*)&Yout[(size_t)(row+8)*DM + col] = v23;
            }
        }
    }
}

// ---------------------------------------------------------------------------
// Flash attention per (b,h): BQ=BK=64, tf32 mma for QK^T and PV,
// smem softmax with fma-pipe exp2 (log2 domain throughout).
// Smem: Qs[64][68] tf32, KPs[64][68] (K tf32 -> S fp32 -> P tf32), Vs[64][68] tf32.
// ---------------------------------------------------------------------------
#define APAD 68

__global__ void __launch_bounds__(256) attn_kernel(const int* __restrict__ mask)
{
    extern __shared__ float smraw[];
    unsigned* Qs  = (unsigned*)smraw;         // [64][APAD]
    unsigned* KPs = Qs  + 64*APAD;            // [64][APAD]
    unsigned* Vs  = KPs + 64*APAD;            // [64][APAD]
    float* s_rb = (float*)(Vs + 64*APAD);     // 68
    float* s_m  = s_rb + 68;                  // 64
    float* s_l  = s_m + 64;                   // 64
    float* s_f  = s_l + 64;                   // 64

    int tid  = threadIdx.x;
    int lane = tid & 31, w = tid >> 5;
    int gid  = lane >> 2, tig = lane & 3;
    int wm   = w >> 1,    wn  = w & 1;        // 4(m) x 2(n)
    int bh = blockIdx.y;
    int b  = bh >> 4, h = bh & 15;
    int q0 = blockIdx.x << 6;

    if (tid < NREL) s_rb[tid] = g_rb[tid];
    if (tid < 64) { s_m[tid] = -1e30f; s_l[tid] = 0.f; }

    // Q tile -> Qs (tf32)
    {
        const float* qp = g_q + ((size_t)bh*SEQ + q0)*DK;
        #pragma unroll
        for (int i = 0; i < 4; i++) {
            int idx = tid + i*256, r = idx >> 4, c = (idx & 15) * 4;
            float4 v = *(const float4*)&qp[r*DK + c];
            uint4 u; u.x=f2tf(v.x); u.y=f2tf(v.y); u.z=f2tf(v.z); u.w=f2tf(v.w);
            *(uint4*)&Qs[r*APAD + c] = u;
        }
    }

    float oacc[4][4] = {};
    const float* kbase = g_k + (size_t)bh*SEQ*DK;
    const float* vbase = g_v + (size_t)bh*SEQ*DK;

    for (int kt = 0; kt < SEQ/64; kt++) {
        int k0 = kt << 6;
        __syncthreads();   // prior-iter P/V reads done; Q/init done on first iter

        // K -> KPs[key][d], V -> Vs[k][d]  (both tf32, natural layout)
        #pragma unroll
        for (int i = 0; i < 4; i++) {
            int idx = tid + i*256, r = idx >> 4, c = (idx & 15) * 4;
            float4 kv = *(const float4*)&kbase[(size_t)(k0 + r)*DK + c];
            uint4 uk; uk.x=f2tf(kv.x); uk.y=f2tf(kv.y); uk.z=f2tf(kv.z); uk.w=f2tf(kv.w);
            *(uint4*)&KPs[r*APAD + c] = uk;
            float4 vv = *(const float4*)&vbase[(size_t)(k0 + r)*DK + c];
            uint4 uv; uv.x=f2tf(vv.x); uv.y=f2tf(vv.y); uv.z=f2tf(vv.z); uv.w=f2tf(vv.w);
            *(uint4*)&Vs[r*APAD + c] = uv;
        }
        __syncthreads();

        // S = Q @ K^T  (warp tile 16x32)
        float sacc[4][4] = {};
        #pragma unroll
        for (int kk = 0; kk < 8; kk++) {
            int kc = kk * 8;
            int r = wm*16 + gid;
            unsigned a0 = Qs[r*APAD + kc + tig];
            unsigned a1 = Qs[(r+8)*APAD + kc + tig];
            unsigned a2 = Qs[r*APAD + kc + tig + 4];
            unsigned a3 = Qs[(r+8)*APAD + kc + tig + 4];
            #pragma unroll
            for (int ni = 0; ni < 4; ni++) {
                int kr = wn*32 + ni*8 + gid;
                unsigned b0 = KPs[kr*APAD + kc + tig];
                unsigned b1 = KPs[kr*APAD + kc + tig + 4];
                mma8(sacc[ni], a0,a1,a2,a3, b0,b1);
            }
        }
        __syncthreads();   // all K fragment reads done -> reuse KPs for S

        // write raw S (fp32) into KPs
        float* Ss = (float*)KPs;
        #pragma unroll
        for (int ni = 0; ni < 4; ni++) {
            int r0 = wm*16 + gid;
            int cc = wn*32 + ni*8 + 2*tig;
            *(float2*)&Ss[r0*APAD + cc]     = make_float2(sacc[ni][0], sacc[ni][1]);
            *(float2*)&Ss[(r0+8)*APAD + cc] = make_float2(sacc[ni][2], sacc[ni][3]);
        }
        __syncthreads();

        // softmax (log2 domain): thread = (row q = tid>>2, 16 k's)
        int q  = tid >> 2;
        int qg = q0 + q;
        int kq = (tid & 3) * 16;
        float* srow = Ss + q*APAD + kq;
        const int* mrow = mask + ((size_t)b*SEQ + qg)*SEQ + k0 + kq;
        float mx = -1e30f;
        #pragma unroll
        for (int j = 0; j < 4; j++) {
            float4 s4 = *(float4*)&srow[j*4];
            int4  m4 = *(const int4*)&mrow[j*4];
            int r0 = qg - (k0 + kq + j*4);
            s4.x = (m4.x==0) ? -3e9f : fmaf(s4.x, SCALE_L2, s_rb[min(max(r0  ,-32),32)+32]);
            s4.y = (m4.y==0) ? -3e9f : fmaf(s4.y, SCALE_L2, s_rb[min(max(r0-1,-32),32)+32]);
            s4.z = (m4.z==0) ? -3e9f : fmaf(s4.z, SCALE_L2, s_rb[min(max(r0-2,-32),32)+32]);
            s4.w = (m4.w==0) ? -3e9f : fmaf(s4.w, SCALE_L2, s_rb[min(max(r0-3,-32),32)+32]);
            *(float4*)&srow[j*4] = s4;
            mx = fmaxf(mx, fmaxf(fmaxf(s4.x, s4.y), fmaxf(s4.z, s4.w)));
        }
        mx = fmaxf(mx, __shfl_xor_sync(0xffffffffu, mx, 1));
        mx = fmaxf(mx, __shfl_xor_sync(0xffffffffu, mx, 2));
        float mold = s_m[q];
        float mnew = fmaxf(mold, mx);
        float fr   = fexp2(mold - mnew);
        float psum = 0.f;
        unsigned* prow = (unsigned*)srow;
        #pragma unroll
        for (int j = 0; j < 4; j++) {
            float4 s4 = *(float4*)&srow[j*4];
            float p0 = fexp2(s4.x - mnew);
            float p1 = fexp2(s4.y - mnew);
            float p2 = fexp2(s4.z - mnew);
            float p3 = fexp2(s4.w - mnew);
            psum += (p0 + p1) + (p2 + p3);
            uint4 u; u.x=f2tf(p0); u.y=f2tf(p1); u.z=f2tf(p2); u.w=f2tf(p3);
            *(uint4*)&prow[j*4] = u;
        }
        psum += __shfl_xor_sync(0xffffffffu, psum, 1);
        psum += __shfl_xor_sync(0xffffffffu, psum, 2);
        if ((tid & 3) == 0) {
            s_m[q] = mnew;
            s_f[q] = fr;
            s_l[q] = s_l[q]*fr + psum;
        }
        __syncthreads();   // P + s_f visible

        // rescale O accumulators
        float f0 = s_f[wm*16 + gid];
        float f1 = s_f[wm*16 + gid + 8];
        #pragma unroll
        for (int ni = 0; ni < 4; ni++) {
            oacc[ni][0] *= f0; oacc[ni][1] *= f0;
            oacc[ni][2] *= f1; oacc[ni][3] *= f1;
        }

        // O += P @ V   (A = P rows q, B = V[k][d], 2-way-conflict b-loads)
        #pragma unroll
        for (int kk = 0; kk < 8; kk++) {
            int kc = kk * 8;
            int r = wm*16 + gid;
            unsigned a0 = KPs[r*APAD + kc + tig];
            unsigned a1 = KPs[(r+8)*APAD + kc + tig];
            unsigned a2 = KPs[r*APAD + kc + tig + 4];
            unsigned a3 = KPs[(r+8)*APAD + kc + tig + 4];
            #pragma unroll
            for (int ni = 0; ni < 4; ni++) {
                int d = wn*32 + ni*8 + gid;
                unsigned b0 = Vs[(kc + tig)*APAD + d];
                unsigned b1 = Vs[(kc + tig + 4)*APAD + d];
                mma8(oacc[ni], a0,a1,a2,a3, b0,b1);
            }
        }
    }
    __syncthreads();

    // normalize + write to g_att[(b,q), h*64+d]
    float il0 = 1.f / s_l[wm*16 + gid];
    float il1 = 1.f / s_l[wm*16 + gid + 8];
    int qA = q0 + wm*16 + gid;
    #pragma unroll
    for (int ni = 0; ni < 4; ni++) {
        int d = wn*32 + ni*8 + 2*tig;
        *(float2*)&g_att[((size_t)b*SEQ + qA)*DM + h*64 + d] =
            make_float2(oacc[ni][0]*il0, oacc[ni][1]*il0);
        *(float2*)&g_att[((size_t)b*SEQ + qA + 8)*DM + h*64 + d] =
            make_float2(oacc[ni][2]*il1, oacc[ni][3]*il1);
    }
}

// ---------------------------------------------------------------------------
extern "C" void kernel_launch(void* const* d_in, const int* in_sizes, int n_in,
                              void* d_out, int out_size)
{
    const float* query = (const float*)d_in[0];
    const float* key   = (const float*)d_in[1];
    const float* value = (const float*)d_in[2];
    const int*   mask  = (const int*)  d_in[3];
    const float* Wq    = (const float*)d_in[4];
    const float* bq    = (const float*)d_in[5];
    const float* Wk    = (const float*)d_in[6];
    const float* bk    = (const float*)d_in[7];
    const float* Wv    = (const float*)d_in[8];
    const float* bv    = (const float*)d_in[9];
    const float* Wo    = (const float*)d_in[10];
    const float* bo    = (const float*)d_in[11];
    const float* rel   = (const float*)d_in[12];
    float* out = (float*)d_out;

    cudaFuncSetAttribute(attn_kernel, cudaFuncAttributeMaxDynamicSharedMemorySize, 56*1024);

    relbias_kernel<<<1, 128>>>(rel);

    dim3 pg(DM/GBN, NROW/GBM);   // (16, 32)
    gemm_tf32_kernel<<<pg, 256>>>(query, Wq, bq, nullptr, 0);
    gemm_tf32_kernel<<<pg, 256>>>(key,   Wk, bk, nullptr, 1);
    gemm_tf32_kernel<<<pg, 256>>>(value, Wv, bv, nullptr, 2);

    size_t smem = (size_t)(3*64*APAD + 68 + 3*64) * sizeof(float);
    attn_kernel<<<dim3(SEQ/64, BATCH*H_), 256, smem>>>(mask);

    gemm_tf32_kernel<<<pg, 256>>>(nullptr, Wo, bo, out, 3);
}

// round 3
// speedup vs baseline: 2.4039x; 1.1358x over previous
#include <cuda_runtime.h>

#define H_    16
#define DM    1024
#define DK    64
#define BATCH 2
#define SEQ   2048
#define NROW  (BATCH*SEQ)   // 4096
#define NREL  65
#define LOG2E 1.4426950408889634f
#define SCALE_L2 (0.125f*LOG2E)

// Scratch (device globals: allocation-free scratch per harness rules)
__device__ float g_q[(size_t)BATCH*H_*SEQ*DK];
__device__ float g_k[(size_t)BATCH*H_*SEQ*DK];
__device__ float g_v[(size_t)BATCH*H_*SEQ*DK];
__device__ float g_att[(size_t)NROW*DM];
__device__ float g_rb[NREL];

// ---------------------------------------------------------------------------
// helpers
// ---------------------------------------------------------------------------
__device__ __forceinline__ unsigned f2tf(float x){
    unsigned r; asm("cvt.rna.tf32.f32 %0, %1;" : "=r"(r) : "f"(x)); return r;
}
__device__ __forceinline__ void mma8(float d[4],
    unsigned a0,unsigned a1,unsigned a2,unsigned a3, unsigned b0,unsigned b1){
    asm volatile("mma.sync.aligned.m16n8k8.row.col.f32.tf32.tf32.f32 "
        "{%0,%1,%2,%3}, {%4,%5,%6,%7}, {%8,%9}, {%0,%1,%2,%3};"
        : "+f"(d[0]),"+f"(d[1]),"+f"(d[2]),"+f"(d[3])
        : "r"(a0),"r"(a1),"r"(a2),"r"(a3),"r"(b0),"r"(b1));
}
// exp2 on the fma/alu pipes (MUFU is only 0.5/cyc/SM on sm_103a)
__device__ __forceinline__ float fexp2(float y){
    y = fmaxf(y, -126.f);
    float z = y + 12582912.f;               // 2^23+2^22 round-to-int trick
    int   e = __float_as_int(z) - 0x4B400000;
    float f = y - (z - 12582912.f);         // in [-0.5, 0.5]
    float p =             1.3333558146e-3f;
    p = fmaf(p, f, 9.6181291918e-3f);
    p = fmaf(p, f, 5.5504108664e-2f);
    p = fmaf(p, f, 2.4022650695e-1f);
    p = fmaf(p, f, 6.9314718056e-1f);
    p = fmaf(p, f, 1.0f);
    return __int_as_float(__float_as_int(p) + (e << 23));
}

// ---------------------------------------------------------------------------
// rel bias (pre-scaled into log2 domain)
// ---------------------------------------------------------------------------
__global__ void relbias_kernel(const float* __restrict__ rel_emb) {
    int i = threadIdx.x;
    if (i < NREL) {
        float s = 0.f;
        #pragma unroll
        for (int d = 0; d < DK; d++) s += rel_emb[i*DK + d];
        g_rb[i] = s * LOG2E;
    }
}

// ---------------------------------------------------------------------------
// GEMM core: Y = X @ W^T + bias, tf32 mma, double-buffered smem pipeline.
// BM=128, BN=64, BK=32, 256 threads, warps 4(m)x2(n), warp tile 32x32.
// ---------------------------------------------------------------------------
#define GBM 128
#define GBN 64
#define GBK 32
#define GPAD 36

template<int SCAT>
__device__ __forceinline__ void gemm_core(const float* __restrict__ X,
    const float* __restrict__ W, const float* __restrict__ bias,
    float* __restrict__ dst)
{
    extern __shared__ unsigned gsm[];
    unsigned* As = gsm;                    // [2][128][GPAD]
    unsigned* Bs = gsm + 2*GBM*GPAD;       // [2][64][GPAD]

    int tid=threadIdx.x, lane=tid&31, w=tid>>5;
    int gid=lane>>2, tig=lane&3, wm=w>>1, wn=w&1;
    int m0=blockIdx.y*GBM, n0=blockIdx.x*GBN;

    int lr=tid>>3, lc=(tid&7)*4;
    const float* xp = X + (size_t)(m0+lr)*DM + lc;
    const float* wp = W + (size_t)(n0+lr)*DM + lc;

    float4 xa[4]; float4 wa[2];
    #pragma unroll
    for (int i=0;i<4;i++) xa[i]=*(const float4*)(xp + (size_t)32*i*DM);
    #pragma unroll
    for (int i=0;i<2;i++) wa[i]=*(const float4*)(wp + (size_t)32*i*DM);

    {   // stage 0
        #pragma unroll
        for (int i=0;i<4;i++){
            uint4 u={f2tf(xa[i].x),f2tf(xa[i].y),f2tf(xa[i].z),f2tf(xa[i].w)};
            *(uint4*)&As[(lr+32*i)*GPAD + lc] = u;
        }
        #pragma unroll
        for (int i=0;i<2;i++){
            uint4 u={f2tf(wa[i].x),f2tf(wa[i].y),f2tf(wa[i].z),f2tf(wa[i].w)};
            *(uint4*)&Bs[(lr+32*i)*GPAD + lc] = u;
        }
    }

    float acc[2][4][4]={};
    #pragma unroll 1
    for (int t=0;t<DM/GBK;t++){
        __syncthreads();
        if (t+1 < DM/GBK){
            int k0=(t+1)*GBK;
            #pragma unroll
            for (int i=0;i<4;i++) xa[i]=*(const float4*)(xp + k0 + (size_t)32*i*DM);
            #pragma unroll
            for (int i=0;i<2;i++) wa[i]=*(const float4*)(wp + k0 + (size_t)32*i*DM);
        }
        unsigned* Ab = As + (t&1)*GBM*GPAD;
        unsigned* Bb = Bs + (t&1)*GBN*GPAD;
        #pragma unroll
        for (int kk=0;kk<4;kk++){
            int kc=kk*8;
            unsigned af[2][4], bf[4][2];
            #pragma unroll
            for (int mi=0;mi<2;mi++){
                int r=wm*32+mi*16+gid;
                af[mi][0]=Ab[r*GPAD+kc+tig];
                af[mi][1]=Ab[(r+8)*GPAD+kc+tig];
                af[mi][2]=Ab[r*GPAD+kc+tig+4];
                af[mi][3]=Ab[(r+8)*GPAD+kc+tig+4];
            }
            #pragma unroll
            for (int ni=0;ni<4;ni++){
                int r=wn*32+ni*8+gid;
                bf[ni][0]=Bb[r*GPAD+kc+tig];
                bf[ni][1]=Bb[r*GPAD+kc+tig+4];
            }
            #pragma unroll
            for (int mi=0;mi<2;mi++)
                #pragma unroll
                for (int ni=0;ni<4;ni++)
                    mma8(acc[mi][ni], af[mi][0],af[mi][1],af[mi][2],af[mi][3],
                         bf[ni][0],bf[ni][1]);
        }
        if (t+1 < DM/GBK){
            int buf=(t+1)&1;
            #pragma unroll
            for (int i=0;i<4;i++){
                uint4 u={f2tf(xa[i].x),f2tf(xa[i].y),f2tf(xa[i].z),f2tf(xa[i].w)};
                *(uint4*)&As[buf*GBM*GPAD + (lr+32*i)*GPAD + lc] = u;
            }
            #pragma unroll
            for (int i=0;i<2;i++){
                uint4 u={f2tf(wa[i].x),f2tf(wa[i].y),f2tf(wa[i].z),f2tf(wa[i].w)};
                *(uint4*)&Bs[buf*GBN*GPAD + (lr+32*i)*GPAD + lc] = u;
            }
        }
    }

    #pragma unroll
    for (int mi=0;mi<2;mi++){
        #pragma unroll
        for (int ni=0;ni<4;ni++){
            int row = m0 + wm*32 + mi*16 + gid;
            int col = n0 + wn*32 + ni*8 + 2*tig;
            float bv0 = bias[col], bv1 = bias[col+1];
            float2 v01 = make_float2(acc[mi][ni][0]+bv0, acc[mi][ni][1]+bv1);
            float2 v23 = make_float2(acc[mi][ni][2]+bv0, acc[mi][ni][3]+bv1);
            if (SCAT){
                int hh = col >> 6, dk = col & 63;
                int b1_ = row >> 11, s1 = row & (SEQ-1);
                *(float2*)&dst[(((size_t)b1_*H_ + hh)*SEQ + s1)*DK + dk] = v01;
                int r2 = row + 8;
                int b2_ = r2 >> 11, s2 = r2 & (SEQ-1);
                *(float2*)&dst[(((size_t)b2_*H_ + hh)*SEQ + s2)*DK + dk] = v23;
            } else {
                *(float2*)&dst[(size_t)row*DM + col]     = v01;
                *(float2*)&dst[(size_t)(row+8)*DM + col] = v23;
            }
        }
    }
}

__global__ void __launch_bounds__(256) gemm_qkv_kernel(
    const float* __restrict__ q, const float* __restrict__ k, const float* __restrict__ v,
    const float* __restrict__ Wq, const float* __restrict__ bq,
    const float* __restrict__ Wk, const float* __restrict__ bk,
    const float* __restrict__ Wv, const float* __restrict__ bv)
{
    int m = blockIdx.z;
    const float* X    = (m==0)? q  : (m==1)? k  : v;
    const float* W    = (m==0)? Wq : (m==1)? Wk : Wv;
    const float* bias = (m==0)? bq : (m==1)? bk : bv;
    float* dst        = (m==0)? g_q : (m==1)? g_k : g_v;
    gemm_core<1>(X, W, bias, dst);
}

__global__ void __launch_bounds__(256) gemm_out_kernel(
    const float* __restrict__ Wo, const float* __restrict__ bo, float* __restrict__ out)
{
    gemm_core<0>(g_att, Wo, bo, out);
}

// ---------------------------------------------------------------------------
// Flash attention: BQ=128, 8 warps, warp tile 16 q-rows x 64 keys.
// Register softmax (row fully inside a 4-lane group), P kept in registers and
// permuted to A-fragment layout via shfl. K/V tiles in smem (tf32).
// ---------------------------------------------------------------------------
#define APAD 68

__global__ void __launch_bounds__(256) attn_kernel(const int* __restrict__ mask)
{
    extern __shared__ unsigned sm_[];
    unsigned* Ks = sm_;                 // [64][APAD]
    unsigned* Vs = sm_ + 64*APAD;       // [64][APAD]
    float* Qstage = (float*)sm_;        // overlay [128][APAD] (same bytes as Ks+Vs)
    float* s_rb = (float*)(sm_ + 2*64*APAD);   // 68

    int tid=threadIdx.x, lane=tid&31, w=tid>>5;
    int gid=lane>>2, tig=lane&3;
    int bh=blockIdx.y, b=bh>>4, h=bh&15;
    int q0=blockIdx.x<<7;

    if (tid < NREL) s_rb[tid] = g_rb[tid];

    // stage Q tile, then pull per-warp fragments into registers (reused 32x)
    {
        const float* qp = g_q + ((size_t)bh*SEQ + q0)*DK;
        #pragma unroll
        for (int i=0;i<8;i++){
            int idx=tid+i*256, r=idx>>4, c=(idx&15)*4;
            *(float4*)&Qstage[r*APAD+c] = *(const float4*)&qp[(size_t)r*DK+c];
        }
    }
    __syncthreads();
    int r0 = w*16 + gid;
    unsigned qa[8][4];
    #pragma unroll
    for (int j=0;j<8;j++){
        qa[j][0]=f2tf(Qstage[r0*APAD + 8*j+tig]);
        qa[j][1]=f2tf(Qstage[(r0+8)*APAD + 8*j+tig]);
        qa[j][2]=f2tf(Qstage[r0*APAD + 8*j+tig+4]);
        qa[j][3]=f2tf(Qstage[(r0+8)*APAD + 8*j+tig+4]);
    }

    float oacc[8][4]={};
    float m0=-1e30f, m1=-1e30f, l0=0.f, l1=0.f;
    const float* kbase = g_k + (size_t)bh*SEQ*DK;
    const float* vbase = g_v + (size_t)bh*SEQ*DK;
    int qg0 = q0 + r0;
    const int* mrow0 = mask + ((size_t)b*SEQ + qg0)*SEQ;
    const int* mrow1 = mrow0 + 8*SEQ;
    int srcA = (lane & ~3) | (tig>>1);
    int srcB = srcA + 2;

    for (int kt=0; kt<SEQ/64; kt++){
        int k0 = kt<<6;
        __syncthreads();   // prior-iter K/V (and Qstage on iter 0) reads done
        #pragma unroll
        for (int i=0;i<4;i++){
            int idx=tid+i*256, r=idx>>4, c=(idx&15)*4;
            float4 kv = *(const float4*)&kbase[(size_t)(k0+r)*DK+c];
            uint4 uk={f2tf(kv.x),f2tf(kv.y),f2tf(kv.z),f2tf(kv.w)};
            *(uint4*)&Ks[r*APAD+c]=uk;
            float4 vv = *(const float4*)&vbase[(size_t)(k0+r)*DK+c];
            uint4 uv={f2tf(vv.x),f2tf(vv.y),f2tf(vv.z),f2tf(vv.w)};
            *(uint4*)&Vs[r*APAD+c]=uv;
        }
        __syncthreads();

        // mask prefetch (L2-resident; reused by all 16 heads)
        int2 mk0[8], mk1[8];
        #pragma unroll
        for (int nt=0;nt<8;nt++){
            int c = k0 + nt*8 + 2*tig;
            mk0[nt]=*(const int2*)&mrow0[c];
            mk1[nt]=*(const int2*)&mrow1[c];
        }

        // S = Q @ K^T : warp tile 16x64
        float sacc[8][4]={};
        #pragma unroll
        for (int j=0;j<8;j++){
            #pragma unroll
            for (int nt=0;nt<8;nt++){
                unsigned b0=Ks[(nt*8+gid)*APAD + 8*j+tig];
                unsigned b1=Ks[(nt*8+gid)*APAD + 8*j+tig+4];
                mma8(sacc[nt], qa[j][0],qa[j][1],qa[j][2],qa[j][3], b0,b1);
            }
        }

        // scale + bias + mask, register softmax (rows live in 4-lane groups)
        float mx0=-1e30f, mx1=-1e30f;
        #pragma unroll
        for (int nt=0;nt<8;nt++){
            int c = k0 + nt*8 + 2*tig;
            int ra = qg0 - c;
            float b00=s_rb[min(max(ra  ,-32),32)+32];
            float b01=s_rb[min(max(ra-1,-32),32)+32];
            float b10=s_rb[min(max(ra+8,-32),32)+32];
            float b11=s_rb[min(max(ra+7,-32),32)+32];
            sacc[nt][0] = (mk0[nt].x==0) ? -3e9f : fmaf(sacc[nt][0],SCALE_L2,b00);
            sacc[nt][1] = (mk0[nt].y==0) ? -3e9f : fmaf(sacc[nt][1],SCALE_L2,b01);
            sacc[nt][2] = (mk1[nt].x==0) ? -3e9f : fmaf(sacc[nt][2],SCALE_L2,b10);
            sacc[nt][3] = (mk1[nt].y==0) ? -3e9f : fmaf(sacc[nt][3],SCALE_L2,b11);
            mx0=fmaxf(mx0,fmaxf(sacc[nt][0],sacc[nt][1]));
            mx1=fmaxf(mx1,fmaxf(sacc[nt][2],sacc[nt][3]));
        }
        mx0=fmaxf(mx0,__shfl_xor_sync(0xffffffffu,mx0,1));
        mx0=fmaxf(mx0,__shfl_xor_sync(0xffffffffu,mx0,2));
        mx1=fmaxf(mx1,__shfl_xor_sync(0xffffffffu,mx1,1));
        mx1=fmaxf(mx1,__shfl_xor_sync(0xffffffffu,mx1,2));
        float mn0=fmaxf(m0,mx0), mn1=fmaxf(m1,mx1);
        float fr0=fexp2(m0-mn0), fr1=fexp2(m1-mn1);
        m0=mn0; m1=mn1;
        float ps0=0.f, ps1=0.f;
        unsigned (*pu)[4] = (unsigned(*)[4])sacc;   // reuse storage for tf32 P
        #pragma unroll
        for (int nt=0;nt<8;nt++){
            float p0=fexp2(sacc[nt][0]-mn0);
            float p1=fexp2(sacc[nt][1]-mn0);
            float p2=fexp2(sacc[nt][2]-mn1);
            float p3=fexp2(sacc[nt][3]-mn1);
            ps0 += p0+p1; ps1 += p2+p3;
            oacc[nt][0]*=fr0; oacc[nt][1]*=fr0; oacc[nt][2]*=fr1; oacc[nt][3]*=fr1;
            pu[nt][0]=f2tf(p0); pu[nt][1]=f2tf(p1); pu[nt][2]=f2tf(p2); pu[nt][3]=f2tf(p3);
        }
        ps0 += __shfl_xor_sync(0xffffffffu,ps0,1);
        ps0 += __shfl_xor_sync(0xffffffffu,ps0,2);
        ps1 += __shfl_xor_sync(0xffffffffu,ps1,1);
        ps1 += __shfl_xor_sync(0xffffffffu,ps1,2);
        l0 = l0*fr0 + ps0; l1 = l1*fr1 + ps1;

        // O += P @ V : P permuted acc->A-frag layout via intra-group shfl
        #pragma unroll
        for (int j=0;j<8;j++){
            unsigned sA0=__shfl_sync(0xffffffffu,pu[j][0],srcA);
            unsigned sA1=__shfl_sync(0xffffffffu,pu[j][1],srcA);
            unsigned sA2=__shfl_sync(0xffffffffu,pu[j][2],srcA);
            unsigned sA3=__shfl_sync(0xffffffffu,pu[j][3],srcA);
            unsigned sB0=__shfl_sync(0xffffffffu,pu[j][0],srcB);
            unsigned sB1=__shfl_sync(0xffffffffu,pu[j][1],srcB);
            unsigned sB2=__shfl_sync(0xffffffffu,pu[j][2],srcB);
            unsigned sB3=__shfl_sync(0xffffffffu,pu[j][3],srcB);
            bool hi = (tig & 1);
            unsigned a0 = hi? sA1 : sA0;
            unsigned a1 = hi? sA3 : sA2;
            unsigned a2 = hi? sB1 : sB0;
            unsigned a3 = hi? sB3 : sB2;
            #pragma unroll
            for (int nt=0;nt<8;nt++){
                unsigned b0=Vs[(8*j+tig)*APAD + nt*8+gid];
                unsigned b1=Vs[(8*j+tig+4)*APAD + nt*8+gid];
                mma8(oacc[nt], a0,a1,a2,a3, b0,b1);
            }
        }
    }

    float il0=1.f/l0, il1=1.f/l1;
    float* op = g_att + ((size_t)b*SEQ + qg0)*DM + h*64;
    #pragma unroll
    for (int nt=0;nt<8;nt++){
        int d=nt*8+2*tig;
        *(float2*)&op[d] = make_float2(oacc[nt][0]*il0, oacc[nt][1]*il0);
        *(float2*)&op[(size_t)8*DM + d] = make_float2(oacc[nt][2]*il1, oacc[nt][3]*il1);
    }
}

// ---------------------------------------------------------------------------
extern "C" void kernel_launch(void* const* d_in, const int* in_sizes, int n_in,
                              void* d_out, int out_size)
{
    const float* query = (const float*)d_in[0];
    const float* key   = (const float*)d_in[1];
    const float* value = (const float*)d_in[2];
    const int*   mask  = (const int*)  d_in[3];
    const float* Wq    = (const float*)d_in[4];
    const float* bq    = (const float*)d_in[5];
    const float* Wk    = (const float*)d_in[6];
    const float* bk    = (const float*)d_in[7];
    const float* Wv    = (const float*)d_in[8];
    const float* bv    = (const float*)d_in[9];
    const float* Wo    = (const float*)d_in[10];
    const float* bo    = (const float*)d_in[11];
    const float* rel   = (const float*)d_in[12];
    float* out = (float*)d_out;

    size_t gsmem = (size_t)(2*GBM*GPAD + 2*GBN*GPAD) * 4;   // 55296 B
    cudaFuncSetAttribute(gemm_qkv_kernel, cudaFuncAttributeMaxDynamicSharedMemorySize, (int)gsmem);
    cudaFuncSetAttribute(gemm_out_kernel, cudaFuncAttributeMaxDynamicSharedMemorySize, (int)gsmem);

    relbias_kernel<<<1, 128>>>(rel);

    dim3 pg(DM/GBN, NROW/GBM, 3);   // (16, 32, 3)
    gemm_qkv_kernel<<<pg, 256, gsmem>>>(query, key, value, Wq, bq, Wk, bk, Wv, bv);

    size_t asmem = (size_t)(2*64*APAD)*4 + 68*4;   // 35088 B
    attn_kernel<<<dim3(SEQ/128, BATCH*H_), 256, asmem>>>(mask);

    gemm_out_kernel<<<dim3(DM/GBN, NROW/GBM), 256, gsmem>>>(Wo, bo, out);
}

// round 4
// speedup vs baseline: 2.8464x; 1.1841x over previous
#include <cuda_runtime.h>

#define H_    16
#define DM    1024
#define DK    64
#define BATCH 2
#define SEQ   2048
#define NROW  (BATCH*SEQ)   // 4096
#define NREL  65
#define LOG2E 1.4426950408889634f
#define SCALE_L2 (0.125f*LOG2E)

// Scratch (device globals: allocation-free scratch per harness rules)
__device__ float g_q[(size_t)BATCH*H_*SEQ*DK];
__device__ float g_k[(size_t)BATCH*H_*SEQ*DK];
__device__ float g_v[(size_t)BATCH*H_*SEQ*DK];
__device__ float g_att[(size_t)NROW*DM];
__device__ float g_rb[NREL];
// tf32-pre-rounded copies of inputs
__device__ float g_cq[(size_t)NROW*DM];
__device__ float g_ck[(size_t)NROW*DM];
__device__ float g_cv[(size_t)NROW*DM];
__device__ float g_cwq[(size_t)DM*DM];
__device__ float g_cwk[(size_t)DM*DM];
__device__ float g_cwv[(size_t)DM*DM];
__device__ float g_cwo[(size_t)DM*DM];

// ---------------------------------------------------------------------------
// helpers
// ---------------------------------------------------------------------------
__device__ __forceinline__ unsigned f2tf(float x){
    unsigned r; asm("cvt.rna.tf32.f32 %0, %1;" : "=r"(r) : "f"(x)); return r;
}
__device__ __forceinline__ void mma8(float d[4],
    unsigned a0,unsigned a1,unsigned a2,unsigned a3, unsigned b0,unsigned b1){
    asm volatile("mma.sync.aligned.m16n8k8.row.col.f32.tf32.tf32.f32 "
        "{%0,%1,%2,%3}, {%4,%5,%6,%7}, {%8,%9}, {%0,%1,%2,%3};"
        : "+f"(d[0]),"+f"(d[1]),"+f"(d[2]),"+f"(d[3])
        : "r"(a0),"r"(a1),"r"(a2),"r"(a3),"r"(b0),"r"(b1));
}
__device__ __forceinline__ void cp16(void* sp, const void* gp){
    unsigned s = (unsigned)__cvta_generic_to_shared(sp);
    asm volatile("cp.async.ca.shared.global [%0], [%1], 16;" :: "r"(s), "l"(gp));
}
#define CP_COMMIT() asm volatile("cp.async.commit_group;")
#define CP_WAIT0()  asm volatile("cp.async.wait_group 0;")

// exp2 on the fma/alu pipes (MUFU is only 0.5/cyc/SM on sm_103a)
__device__ __forceinline__ float fexp2(float y){
    y = fmaxf(y, -126.f);
    float z = y + 12582912.f;
    int   e = __float_as_int(z) - 0x4B400000;
    float f = y - (z - 12582912.f);
    float p =             1.3333558146e-3f;
    p = fmaf(p, f, 9.6181291918e-3f);
    p = fmaf(p, f, 5.5504108664e-2f);
    p = fmaf(p, f, 2.4022650695e-1f);
    p = fmaf(p, f, 6.9314718056e-1f);
    p = fmaf(p, f, 1.0f);
    return __int_as_float(__float_as_int(p) + (e << 23));
}

// ---------------------------------------------------------------------------
// prepass: tf32-round inputs (z selects array)
// ---------------------------------------------------------------------------
__global__ void cvt_prepass(const float* __restrict__ q, const float* __restrict__ k,
                            const float* __restrict__ v, const float* __restrict__ wq,
                            const float* __restrict__ wk, const float* __restrict__ wv,
                            const float* __restrict__ wo)
{
    int z = blockIdx.z;
    const float4* src; float4* dst; int n4;
    switch (z) {
        case 0: src=(const float4*)q;  dst=(float4*)g_cq;  n4=NROW*DM/4; break;
        case 1: src=(const float4*)k;  dst=(float4*)g_ck;  n4=NROW*DM/4; break;
        case 2: src=(const float4*)v;  dst=(float4*)g_cv;  n4=NROW*DM/4; break;
        case 3: src=(const float4*)wq; dst=(float4*)g_cwq; n4=DM*DM/4;   break;
        case 4: src=(const float4*)wk; dst=(float4*)g_cwk; n4=DM*DM/4;   break;
        case 5: src=(const float4*)wv; dst=(float4*)g_cwv; n4=DM*DM/4;   break;
        default:src=(const float4*)wo; dst=(float4*)g_cwo; n4=DM*DM/4;   break;
    }
    for (int i = blockIdx.x*blockDim.x + threadIdx.x; i < n4; i += gridDim.x*blockDim.x){
        float4 a = src[i];
        a.x = __uint_as_float(f2tf(a.x));
        a.y = __uint_as_float(f2tf(a.y));
        a.z = __uint_as_float(f2tf(a.z));
        a.w = __uint_as_float(f2tf(a.w));
        dst[i] = a;
    }
}

// ---------------------------------------------------------------------------
// rel bias (pre-scaled into log2 domain)
// ---------------------------------------------------------------------------
__global__ void relbias_kernel(const float* __restrict__ rel_emb) {
    int i = threadIdx.x;
    if (i < NREL) {
        float s = 0.f;
        #pragma unroll
        for (int d = 0; d < DK; d++) s += rel_emb[i*DK + d];
        g_rb[i] = s * LOG2E;
    }
}

// ---------------------------------------------------------------------------
// GEMM core: Y = X @ W^T + bias, tf32 mma, cp.async 2-stage, 1 sync/iter.
// Inputs pre-rounded to tf32. BM=128, BN=64, BK=32, 256 threads.
// ---------------------------------------------------------------------------
#define GBM 128
#define GBN 64
#define GBK 32
#define GPAD 36

template<int SCAT>
__device__ __forceinline__ void gemm_core(const float* __restrict__ X,
    const float* __restrict__ W, const float* __restrict__ bias,
    float* __restrict__ dst)
{
    extern __shared__ unsigned gsm[];
    unsigned* As = gsm;                    // [2][128][GPAD]
    unsigned* Bs = gsm + 2*GBM*GPAD;       // [2][64][GPAD]

    int tid=threadIdx.x, lane=tid&31, w=tid>>5;
    int gid=lane>>2, tig=lane&3, wm=w>>1, wn=w&1;
    int m0=blockIdx.y*GBM, n0=blockIdx.x*GBN;

    int lr=tid>>3, lc=(tid&7)*4;
    const float* xp = X + (size_t)(m0+lr)*DM + lc;
    const float* wp = W + (size_t)(n0+lr)*DM + lc;

    auto issue = [&](int t, int buf){
        int k0 = t*GBK;
        #pragma unroll
        for (int i=0;i<4;i++)
            cp16(&As[buf*GBM*GPAD + (lr+32*i)*GPAD + lc], xp + k0 + (size_t)32*i*DM);
        #pragma unroll
        for (int i=0;i<2;i++)
            cp16(&Bs[buf*GBN*GPAD + (lr+32*i)*GPAD + lc], wp + k0 + (size_t)32*i*DM);
        CP_COMMIT();
    };

    issue(0, 0);

    float acc[2][4][4]={};
    #pragma unroll 1
    for (int t=0;t<DM/GBK;t++){
        CP_WAIT0();
        __syncthreads();
        if (t+1 < DM/GBK) issue(t+1, (t+1)&1);

        unsigned* Ab = As + (t&1)*GBM*GPAD;
        unsigned* Bb = Bs + (t&1)*GBN*GPAD;
        #pragma unroll
        for (int kk=0;kk<4;kk++){
            int kc=kk*8;
            unsigned af[2][4], bf[4][2];
            #pragma unroll
            for (int mi=0;mi<2;mi++){
                int r=wm*32+mi*16+gid;
                af[mi][0]=Ab[r*GPAD+kc+tig];
                af[mi][1]=Ab[(r+8)*GPAD+kc+tig];
                af[mi][2]=Ab[r*GPAD+kc+tig+4];
                af[mi][3]=Ab[(r+8)*GPAD+kc+tig+4];
            }
            #pragma unroll
            for (int ni=0;ni<4;ni++){
                int r=wn*32+ni*8+gid;
                bf[ni][0]=Bb[r*GPAD+kc+tig];
                bf[ni][1]=Bb[r*GPAD+kc+tig+4];
            }
            #pragma unroll
            for (int mi=0;mi<2;mi++)
                #pragma unroll
                for (int ni=0;ni<4;ni++)
                    mma8(acc[mi][ni], af[mi][0],af[mi][1],af[mi][2],af[mi][3],
                         bf[ni][0],bf[ni][1]);
        }
    }

    #pragma unroll
    for (int mi=0;mi<2;mi++){
        #pragma unroll
        for (int ni=0;ni<4;ni++){
            int row = m0 + wm*32 + mi*16 + gid;
            int col = n0 + wn*32 + ni*8 + 2*tig;
            float bv0 = bias[col], bv1 = bias[col+1];
            float y0 = acc[mi][ni][0]+bv0, y1 = acc[mi][ni][1]+bv1;
            float y2 = acc[mi][ni][2]+bv0, y3 = acc[mi][ni][3]+bv1;
            if (SCAT){
                // round for downstream tf32 consumption
                float2 v01 = make_float2(__uint_as_float(f2tf(y0)), __uint_as_float(f2tf(y1)));
                float2 v23 = make_float2(__uint_as_float(f2tf(y2)), __uint_as_float(f2tf(y3)));
                int hh = col >> 6, dk = col & 63;
                int b1_ = row >> 11, s1 = row & (SEQ-1);
                *(float2*)&dst[(((size_t)b1_*H_ + hh)*SEQ + s1)*DK + dk] = v01;
                int r2 = row + 8;
                int b2_ = r2 >> 11, s2 = r2 & (SEQ-1);
                *(float2*)&dst[(((size_t)b2_*H_ + hh)*SEQ + s2)*DK + dk] = v23;
            } else {
                *(float2*)&dst[(size_t)row*DM + col]     = make_float2(y0,y1);
                *(float2*)&dst[(size_t)(row+8)*DM + col] = make_float2(y2,y3);
            }
        }
    }
}

__global__ void __launch_bounds__(256) gemm_qkv_kernel(
    const float* __restrict__ bq, const float* __restrict__ bk, const float* __restrict__ bv)
{
    int m = blockIdx.z;
    const float* X    = (m==0)? g_cq  : (m==1)? g_ck  : g_cv;
    const float* W    = (m==0)? g_cwq : (m==1)? g_cwk : g_cwv;
    const float* bias = (m==0)? bq    : (m==1)? bk    : bv;
    float* dst        = (m==0)? g_q   : (m==1)? g_k   : g_v;
    gemm_core<1>(X, W, bias, dst);
}

__global__ void __launch_bounds__(256) gemm_out_kernel(
    const float* __restrict__ bo, float* __restrict__ out)
{
    gemm_core<0>(g_att, g_cwo, bo, out);
}

// ---------------------------------------------------------------------------
// Flash attention: BQ=128, 8 warps, warp tile 16 q-rows x 64 keys.
// cp.async double-buffered K/V (pre-rounded tf32 bits), 1 sync/iter,
// register softmax, const-bias fast path for off-diagonal tiles.
// ---------------------------------------------------------------------------
#define APAD 68

__global__ void __launch_bounds__(256) attn_kernel(const int* __restrict__ mask)
{
    extern __shared__ unsigned sm_[];
    unsigned* KV = sm_;                 // [2 stages][K(64*APAD) V(64*APAD)]
    float* Qstage = (float*)sm_;        // overlay [128][APAD] over stage 0
    float* s_rb = (float*)(sm_ + 4*64*APAD);   // 68

    int tid=threadIdx.x, lane=tid&31, w=tid>>5;
    int gid=lane>>2, tig=lane&3;
    int bh=blockIdx.y, b=bh>>4, h=bh&15;
    int q0=blockIdx.x<<7;

    if (tid < NREL) s_rb[tid] = g_rb[tid];

    const float* kbase = g_k + (size_t)bh*SEQ*DK;
    const float* vbase = g_v + (size_t)bh*SEQ*DK;

    // stage Q via cp.async, pull fragments (pre-rounded -> no cvt)
    {
        const float* qp = g_q + ((size_t)bh*SEQ + q0)*DK;
        #pragma unroll
        for (int i=0;i<8;i++){
            int idx=tid+i*256, r=idx>>4, c=(idx&15)*4;
            cp16(&Qstage[r*APAD+c], qp + (size_t)r*DK + c);
        }
        CP_COMMIT();
        CP_WAIT0();
        __syncthreads();
    }
    int r0 = w*16 + gid;
    unsigned qa[8][4];
    {
        unsigned* Qu = (unsigned*)Qstage;
        #pragma unroll
        for (int j=0;j<8;j++){
            qa[j][0]=Qu[r0*APAD + 8*j+tig];
            qa[j][1]=Qu[(r0+8)*APAD + 8*j+tig];
            qa[j][2]=Qu[r0*APAD + 8*j+tig+4];
            qa[j][3]=Qu[(r0+8)*APAD + 8*j+tig+4];
        }
    }
    __syncthreads();   // all warps done reading Qstage

    auto issue_kv = [&](int kt, int st){
        const float* kp = kbase + (size_t)(kt<<6)*DK;
        const float* vp = vbase + (size_t)(kt<<6)*DK;
        unsigned* Kst = KV + st*2*64*APAD;
        unsigned* Vst = Kst + 64*APAD;
        #pragma unroll
        for (int i=0;i<4;i++){
            int idx=tid+i*256, r=idx>>4, c=(idx&15)*4;
            cp16(&Kst[r*APAD+c], kp + (size_t)r*DK + c);
            cp16(&Vst[r*APAD+c], vp + (size_t)r*DK + c);
        }
        CP_COMMIT();
    };
    issue_kv(0, 0);

    float oacc[8][4]={};
    float m0=-1e30f, m1=-1e30f, l0=0.f, l1=0.f;
    int qg0 = q0 + r0;
    const int* mrow0 = mask + ((size_t)b*SEQ + qg0)*SEQ;
    const int* mrow1 = mrow0 + 8*SEQ;
    int srcA = (lane & ~3) | (tig>>1);
    int srcB = srcA + 2;
    float rb_lo = s_rb[0];   // rel <= -32
    // rb_hi read after the rb store is visible (sync above)
    float rb_hi = s_rb[64];  // rel >= 32

    #pragma unroll 1
    for (int kt=0; kt<SEQ/64; kt++){
        int k0 = kt<<6;
        CP_WAIT0();
        __syncthreads();
        if (kt+1 < SEQ/64) issue_kv(kt+1, (kt+1)&1);

        unsigned* Kst = KV + (kt&1)*2*64*APAD;
        unsigned* Vst = Kst + 64*APAD;

        // mask prefetch (L2-resident)
        int2 mk0[8], mk1[8];
        #pragma unroll
        for (int nt=0;nt<8;nt++){
            int c = k0 + nt*8 + 2*tig;
            mk0[nt]=*(const int2*)&mrow0[c];
            mk1[nt]=*(const int2*)&mrow1[c];
        }

        // S = Q @ K^T : warp tile 16x64
        float sacc[8][4]={};
        #pragma unroll
        for (int j=0;j<8;j++){
            #pragma unroll
            for (int nt=0;nt<8;nt++){
                unsigned b0=Kst[(nt*8+gid)*APAD + 8*j+tig];
                unsigned b1=Kst[(nt*8+gid)*APAD + 8*j+tig+4];
                mma8(sacc[nt], qa[j][0],qa[j][1],qa[j][2],qa[j][3], b0,b1);
            }
        }

        // scale + bias + mask
        float mx0=-1e30f, mx1=-1e30f;
        int dlo = qg0 - (k0+63);       // min rel over warp rows/tile cols
        int dhi = qg0 + 15 - k0;       // max rel
        if (dlo >= 32 || dhi <= -32) {
            float bc = (dlo >= 32) ? rb_hi : rb_lo;
            #pragma unroll
            for (int nt=0;nt<8;nt++){
                sacc[nt][0] = (mk0[nt].x==0) ? -3e9f : fmaf(sacc[nt][0],SCALE_L2,bc);
                sacc[nt][1] = (mk0[nt].y==0) ? -3e9f : fmaf(sacc[nt][1],SCALE_L2,bc);
                sacc[nt][2] = (mk1[nt].x==0) ? -3e9f : fmaf(sacc[nt][2],SCALE_L2,bc);
                sacc[nt][3] = (mk1[nt].y==0) ? -3e9f : fmaf(sacc[nt][3],SCALE_L2,bc);
                mx0=fmaxf(mx0,fmaxf(sacc[nt][0],sacc[nt][1]));
                mx1=fmaxf(mx1,fmaxf(sacc[nt][2],sacc[nt][3]));
            }
        } else {
            #pragma unroll
            for (int nt=0;nt<8;nt++){
                int c = k0 + nt*8 + 2*tig;
                int ra = qg0 - c;
                float b00=s_rb[min(max(ra  ,-32),32)+32];
                float b01=s_rb[min(max(ra-1,-32),32)+32];
                float b10=s_rb[min(max(ra+8,-32),32)+32];
                float b11=s_rb[min(max(ra+7,-32),32)+32];
                sacc[nt][0] = (mk0[nt].x==0) ? -3e9f : fmaf(sacc[nt][0],SCALE_L2,b00);
                sacc[nt][1] = (mk0[nt].y==0) ? -3e9f : fmaf(sacc[nt][1],SCALE_L2,b01);
                sacc[nt][2] = (mk1[nt].x==0) ? -3e9f : fmaf(sacc[nt][2],SCALE_L2,b10);
                sacc[nt][3] = (mk1[nt].y==0) ? -3e9f : fmaf(sacc[nt][3],SCALE_L2,b11);
                mx0=fmaxf(mx0,fmaxf(sacc[nt][0],sacc[nt][1]));
                mx1=fmaxf(mx1,fmaxf(sacc[nt][2],sacc[nt][3]));
            }
        }
        mx0=fmaxf(mx0,__shfl_xor_sync(0xffffffffu,mx0,1));
        mx0=fmaxf(mx0,__shfl_xor_sync(0xffffffffu,mx0,2));
        mx1=fmaxf(mx1,__shfl_xor_sync(0xffffffffu,mx1,1));
        mx1=fmaxf(mx1,__shfl_xor_sync(0xffffffffu,mx1,2));
        float mn0=fmaxf(m0,mx0), mn1=fmaxf(m1,mx1);
        float fr0=fexp2(m0-mn0), fr1=fexp2(m1-mn1);
        m0=mn0; m1=mn1;
        float ps0=0.f, ps1=0.f;
        unsigned (*pu)[4] = (unsigned(*)[4])sacc;
        #pragma unroll
        for (int nt=0;nt<8;nt++){
            float p0=fexp2(sacc[nt][0]-mn0);
            float p1=fexp2(sacc[nt][1]-mn0);
            float p2=fexp2(sacc[nt][2]-mn1);
            float p3=fexp2(sacc[nt][3]-mn1);
            ps0 += p0+p1; ps1 += p2+p3;
            oacc[nt][0]*=fr0; oacc[nt][1]*=fr0; oacc[nt][2]*=fr1; oacc[nt][3]*=fr1;
            pu[nt][0]=f2tf(p0); pu[nt][1]=f2tf(p1); pu[nt][2]=f2tf(p2); pu[nt][3]=f2tf(p3);
        }
        ps0 += __shfl_xor_sync(0xffffffffu,ps0,1);
        ps0 += __shfl_xor_sync(0xffffffffu,ps0,2);
        ps1 += __shfl_xor_sync(0xffffffffu,ps1,1);
        ps1 += __shfl_xor_sync(0xffffffffu,ps1,2);
        l0 = l0*fr0 + ps0; l1 = l1*fr1 + ps1;

        // O += P @ V : P permuted acc->A-frag layout via intra-group shfl
        #pragma unroll
        for (int j=0;j<8;j++){
            unsigned sA0=__shfl_sync(0xffffffffu,pu[j][0],srcA);
            unsigned sA1=__shfl_sync(0xffffffffu,pu[j][1],srcA);
            unsigned sA2=__shfl_sync(0xffffffffu,pu[j][2],srcA);
            unsigned sA3=__shfl_sync(0xffffffffu,pu[j][3],srcA);
            unsigned sB0=__shfl_sync(0xffffffffu,pu[j][0],srcB);
            unsigned sB1=__shfl_sync(0xffffffffu,pu[j][1],srcB);
            unsigned sB2=__shfl_sync(0xffffffffu,pu[j][2],srcB);
            unsigned sB3=__shfl_sync(0xffffffffu,pu[j][3],srcB);
            bool hi = (tig & 1);
            unsigned a0 = hi? sA1 : sA0;
            unsigned a1 = hi? sA3 : sA2;
            unsigned a2 = hi? sB1 : sB0;
            unsigned a3 = hi? sB3 : sB2;
            #pragma unroll
            for (int nt=0;nt<8;nt++){
                unsigned b0=Vst[(8*j+tig)*APAD + nt*8+gid];
                unsigned b1=Vst[(8*j+tig+4)*APAD + nt*8+gid];
                mma8(oacc[nt], a0,a1,a2,a3, b0,b1);
            }
        }
    }

    float il0=1.f/l0, il1=1.f/l1;
    float* op = g_att + ((size_t)b*SEQ + qg0)*DM + h*64;
    #pragma unroll
    for (int nt=0;nt<8;nt++){
        int d=nt*8+2*tig;
        *(float2*)&op[d] = make_float2(
            __uint_as_float(f2tf(oacc[nt][0]*il0)),
            __uint_as_float(f2tf(oacc[nt][1]*il0)));
        *(float2*)&op[(size_t)8*DM + d] = make_float2(
            __uint_as_float(f2tf(oacc[nt][2]*il1)),
            __uint_as_float(f2tf(oacc[nt][3]*il1)));
    }
}

// ---------------------------------------------------------------------------
extern "C" void kernel_launch(void* const* d_in, const int* in_sizes, int n_in,
                              void* d_out, int out_size)
{
    const float* query = (const float*)d_in[0];
    const float* key   = (const float*)d_in[1];
    const float* value = (const float*)d_in[2];
    const int*   mask  = (const int*)  d_in[3];
    const float* Wq    = (const float*)d_in[4];
    const float* bq    = (const float*)d_in[5];
    const float* Wk    = (const float*)d_in[6];
    const float* bk    = (const float*)d_in[7];
    const float* Wv    = (const float*)d_in[8];
    const float* bv    = (const float*)d_in[9];
    const float* Wo    = (const float*)d_in[10];
    const float* bo    = (const float*)d_in[11];
    const float* rel   = (const float*)d_in[12];
    float* out = (float*)d_out;

    size_t gsmem = (size_t)(2*GBM*GPAD + 2*GBN*GPAD) * 4;   // 55296 B
    size_t asmem = (size_t)(4*64*APAD + 68) * 4;            // 69904 B
    cudaFuncSetAttribute(gemm_qkv_kernel, cudaFuncAttributeMaxDynamicSharedMemorySize, (int)gsmem);
    cudaFuncSetAttribute(gemm_out_kernel, cudaFuncAttributeMaxDynamicSharedMemorySize, (int)gsmem);
    cudaFuncSetAttribute(attn_kernel, cudaFuncAttributeMaxDynamicSharedMemorySize, (int)asmem);

    relbias_kernel<<<1, 128>>>(rel);
    cvt_prepass<<<dim3(1024,1,7), 256>>>(query, key, value, Wq, Wk, Wv, Wo);

    dim3 pg(DM/GBN, NROW/GBM, 3);   // (16, 32, 3)
    gemm_qkv_kernel<<<pg, 256, gsmem>>>(bq, bk, bv);

    attn_kernel<<<dim3(SEQ/128, BATCH*H_), 256, asmem>>>(mask);

    gemm_out_kernel<<<dim3(DM/GBN, NROW/GBM), 256, gsmem>>>(bo, out);
}

// round 5
// speedup vs baseline: 2.8861x; 1.0139x over previous
#include <cuda_runtime.h>

#define H_    16
#define DM    1024
#define DK    64
#define BATCH 2
#define SEQ   2048
#define NROW  (BATCH*SEQ)   // 4096
#define NREL  65
#define LOG2E 1.4426950408889634f
#define SCALE_L2 (0.125f*LOG2E)

// Scratch (device globals: allocation-free scratch per harness rules)
__device__ float g_q[(size_t)BATCH*H_*SEQ*DK];
__device__ float g_k[(size_t)BATCH*H_*SEQ*DK];
__device__ float g_v[(size_t)BATCH*H_*SEQ*DK];
__device__ float g_att[(size_t)NROW*DM];
__device__ float g_rb[NREL];
// tf32-pre-rounded copies of inputs
__device__ float g_cq[(size_t)NROW*DM];
__device__ float g_ck[(size_t)NROW*DM];
__device__ float g_cv[(size_t)NROW*DM];
__device__ float g_cwq[(size_t)DM*DM];
__device__ float g_cwk[(size_t)DM*DM];
__device__ float g_cwv[(size_t)DM*DM];
__device__ float g_cwo[(size_t)DM*DM];

// ---------------------------------------------------------------------------
// helpers
// ---------------------------------------------------------------------------
__device__ __forceinline__ unsigned f2tf(float x){
    unsigned r; asm("cvt.rna.tf32.f32 %0, %1;" : "=r"(r) : "f"(x)); return r;
}
__device__ __forceinline__ void mma8(float d[4],
    unsigned a0,unsigned a1,unsigned a2,unsigned a3, unsigned b0,unsigned b1){
    asm volatile("mma.sync.aligned.m16n8k8.row.col.f32.tf32.tf32.f32 "
        "{%0,%1,%2,%3}, {%4,%5,%6,%7}, {%8,%9}, {%0,%1,%2,%3};"
        : "+f"(d[0]),"+f"(d[1]),"+f"(d[2]),"+f"(d[3])
        : "r"(a0),"r"(a1),"r"(a2),"r"(a3),"r"(b0),"r"(b1));
}
__device__ __forceinline__ void cp16(void* sp, const void* gp){
    unsigned s = (unsigned)__cvta_generic_to_shared(sp);
    asm volatile("cp.async.ca.shared.global [%0], [%1], 16;" :: "r"(s), "l"(gp));
}
#define CP_COMMIT() asm volatile("cp.async.commit_group;")
#define CP_WAIT0()  asm volatile("cp.async.wait_group 0;")

// exp2 on the fma/alu pipes (MUFU is only 0.5/cyc/SM on sm_103a)
__device__ __forceinline__ float fexp2(float y){
    y = fmaxf(y, -126.f);
    float z = y + 12582912.f;
    int   e = __float_as_int(z) - 0x4B400000;
    float f = y - (z - 12582912.f);
    float p =             1.3333558146e-3f;
    p = fmaf(p, f, 9.6181291918e-3f);
    p = fmaf(p, f, 5.5504108664e-2f);
    p = fmaf(p, f, 2.4022650695e-1f);
    p = fmaf(p, f, 6.9314718056e-1f);
    p = fmaf(p, f, 1.0f);
    return __int_as_float(__float_as_int(p) + (e << 23));
}

// ---------------------------------------------------------------------------
// prepass: tf32-round inputs (z selects array)
// ---------------------------------------------------------------------------
__global__ void cvt_prepass(const float* __restrict__ q, const float* __restrict__ k,
                            const float* __restrict__ v, const float* __restrict__ wq,
                            const float* __restrict__ wk, const float* __restrict__ wv,
                            const float* __restrict__ wo)
{
    int z = blockIdx.z;
    const float4* src; float4* dst; int n4;
    switch (z) {
        case 0: src=(const float4*)q;  dst=(float4*)g_cq;  n4=NROW*DM/4; break;
        case 1: src=(const float4*)k;  dst=(float4*)g_ck;  n4=NROW*DM/4; break;
        case 2: src=(const float4*)v;  dst=(float4*)g_cv;  n4=NROW*DM/4; break;
        case 3: src=(const float4*)wq; dst=(float4*)g_cwq; n4=DM*DM/4;   break;
        case 4: src=(const float4*)wk; dst=(float4*)g_cwk; n4=DM*DM/4;   break;
        case 5: src=(const float4*)wv; dst=(float4*)g_cwv; n4=DM*DM/4;   break;
        default:src=(const float4*)wo; dst=(float4*)g_cwo; n4=DM*DM/4;   break;
    }
    for (int i = blockIdx.x*blockDim.x + threadIdx.x; i < n4; i += gridDim.x*blockDim.x){
        float4 a = src[i];
        a.x = __uint_as_float(f2tf(a.x));
        a.y = __uint_as_float(f2tf(a.y));
        a.z = __uint_as_float(f2tf(a.z));
        a.w = __uint_as_float(f2tf(a.w));
        dst[i] = a;
    }
}

// ---------------------------------------------------------------------------
// rel bias (pre-scaled into log2 domain)
// ---------------------------------------------------------------------------
__global__ void relbias_kernel(const float* __restrict__ rel_emb) {
    int i = threadIdx.x;
    if (i < NREL) {
        float s = 0.f;
        #pragma unroll
        for (int d = 0; d < DK; d++) s += rel_emb[i*DK + d];
        g_rb[i] = s * LOG2E;
    }
}

// ---------------------------------------------------------------------------
// GEMM core: Y = X @ W^T + bias, tf32 mma, cp.async 2-stage, 1 sync/iter.
// Inputs pre-rounded to tf32. BM=128, BN=64, BK=32, 256 threads.
// ---------------------------------------------------------------------------
#define GBM 128
#define GBN 64
#define GBK 32
#define GPAD 36

template<int SCAT>
__device__ __forceinline__ void gemm_core(const float* __restrict__ X,
    const float* __restrict__ W, const float* __restrict__ bias,
    float* __restrict__ dst)
{
    extern __shared__ unsigned gsm[];
    unsigned* As = gsm;                    // [2][128][GPAD]
    unsigned* Bs = gsm + 2*GBM*GPAD;       // [2][64][GPAD]

    int tid=threadIdx.x, lane=tid&31, w=tid>>5;
    int gid=lane>>2, tig=lane&3, wm=w>>1, wn=w&1;
    int m0=blockIdx.y*GBM, n0=blockIdx.x*GBN;

    int lr=tid>>3, lc=(tid&7)*4;
    const float* xp = X + (size_t)(m0+lr)*DM + lc;
    const float* wp = W + (size_t)(n0+lr)*DM + lc;

    auto issue = [&](int t, int buf){
        int k0 = t*GBK;
        #pragma unroll
        for (int i=0;i<4;i++)
            cp16(&As[buf*GBM*GPAD + (lr+32*i)*GPAD + lc], xp + k0 + (size_t)32*i*DM);
        #pragma unroll
        for (int i=0;i<2;i++)
            cp16(&Bs[buf*GBN*GPAD + (lr+32*i)*GPAD + lc], wp + k0 + (size_t)32*i*DM);
        CP_COMMIT();
    };

    issue(0, 0);

    float acc[2][4][4]={};
    #pragma unroll 1
    for (int t=0;t<DM/GBK;t++){
        CP_WAIT0();
        __syncthreads();
        if (t+1 < DM/GBK) issue(t+1, (t+1)&1);

        unsigned* Ab = As + (t&1)*GBM*GPAD;
        unsigned* Bb = Bs + (t&1)*GBN*GPAD;
        #pragma unroll
        for (int kk=0;kk<4;kk++){
            int kc=kk*8;
            unsigned af[2][4], bf[4][2];
            #pragma unroll
            for (int mi=0;mi<2;mi++){
                int r=wm*32+mi*16+gid;
                af[mi][0]=Ab[r*GPAD+kc+tig];
                af[mi][1]=Ab[(r+8)*GPAD+kc+tig];
                af[mi][2]=Ab[r*GPAD+kc+tig+4];
                af[mi][3]=Ab[(r+8)*GPAD+kc+tig+4];
            }
            #pragma unroll
            for (int ni=0;ni<4;ni++){
                int r=wn*32+ni*8+gid;
                bf[ni][0]=Bb[r*GPAD+kc+tig];
                bf[ni][1]=Bb[r*GPAD+kc+tig+4];
            }
            #pragma unroll
            for (int mi=0;mi<2;mi++)
                #pragma unroll
                for (int ni=0;ni<4;ni++)
                    mma8(acc[mi][ni], af[mi][0],af[mi][1],af[mi][2],af[mi][3],
                         bf[ni][0],bf[ni][1]);
        }
    }

    #pragma unroll
    for (int mi=0;mi<2;mi++){
        #pragma unroll
        for (int ni=0;ni<4;ni++){
            int row = m0 + wm*32 + mi*16 + gid;
            int col = n0 + wn*32 + ni*8 + 2*tig;
            float bv0 = bias[col], bv1 = bias[col+1];
            float y0 = acc[mi][ni][0]+bv0, y1 = acc[mi][ni][1]+bv1;
            float y2 = acc[mi][ni][2]+bv0, y3 = acc[mi][ni][3]+bv1;
            if (SCAT){
                // round for downstream tf32 consumption
                float2 v01 = make_float2(__uint_as_float(f2tf(y0)), __uint_as_float(f2tf(y1)));
                float2 v23 = make_float2(__uint_as_float(f2tf(y2)), __uint_as_float(f2tf(y3)));
                int hh = col >> 6, dk = col & 63;
                int b1_ = row >> 11, s1 = row & (SEQ-1);
                *(float2*)&dst[(((size_t)b1_*H_ + hh)*SEQ + s1)*DK + dk] = v01;
                int r2 = row + 8;
                int b2_ = r2 >> 11, s2 = r2 & (SEQ-1);
                *(float2*)&dst[(((size_t)b2_*H_ + hh)*SEQ + s2)*DK + dk] = v23;
            } else {
                *(float2*)&dst[(size_t)row*DM + col]     = make_float2(y0,y1);
                *(float2*)&dst[(size_t)(row+8)*DM + col] = make_float2(y2,y3);
            }
        }
    }
}

__global__ void __launch_bounds__(256) gemm_qkv_kernel(
    const float* __restrict__ bq, const float* __restrict__ bk, const float* __restrict__ bv)
{
    int m = blockIdx.z;
    const float* X    = (m==0)? g_cq  : (m==1)? g_ck  : g_cv;
    const float* W    = (m==0)? g_cwq : (m==1)? g_cwk : g_cwv;
    const float* bias = (m==0)? bq    : (m==1)? bk    : bv;
    float* dst        = (m==0)? g_q   : (m==1)? g_k   : g_v;
    gemm_core<1>(X, W, bias, dst);
}

__global__ void __launch_bounds__(256) gemm_out_kernel(
    const float* __restrict__ bo, float* __restrict__ out)
{
    gemm_core<0>(g_att, g_cwo, bo, out);
}

// ---------------------------------------------------------------------------
// Flash attention: BQ=128, 8 warps, warp tile 16 q-rows x 64 keys.
// Q fragments in SMEM (frees 32 regs), __launch_bounds__(256,2) -> 2 CTAs/SM.
// cp.async double-buffered K/V, register softmax, const-bias fast path.
// ---------------------------------------------------------------------------
#define APAD 68

__global__ void __launch_bounds__(256, 2) attn_kernel(const int* __restrict__ mask)
{
    extern __shared__ unsigned sm_[];
    unsigned* KV = sm_;                    // [2 stages][K(64*APAD) V(64*APAD)]
    unsigned* Qf = sm_ + 4*64*APAD;        // [8 warps][8j][4][32 lanes] = 8192
    float* Qstage = (float*)sm_;           // overlay [128][APAD] over stage 0
    float* s_rb = (float*)(Qf + 8192);     // 68

    int tid=threadIdx.x, lane=tid&31, w=tid>>5;
    int gid=lane>>2, tig=lane&3;
    int bh=blockIdx.y, b=bh>>4, h=bh&15;
    int q0=blockIdx.x<<7;

    if (tid < NREL) s_rb[tid] = g_rb[tid];

    const float* kbase = g_k + (size_t)bh*SEQ*DK;
    const float* vbase = g_v + (size_t)bh*SEQ*DK;

    // stage Q via cp.async into KV stage-0 overlay, then repack per-warp
    // fragments into Qf (lane-contiguous -> conflict-free reload each tile)
    {
        const float* qp = g_q + ((size_t)bh*SEQ + q0)*DK;
        #pragma unroll
        for (int i=0;i<8;i++){
            int idx=tid+i*256, r=idx>>4, c=(idx&15)*4;
            cp16(&Qstage[r*APAD+c], qp + (size_t)r*DK + c);
        }
        CP_COMMIT();
        CP_WAIT0();
        __syncthreads();
        int r0 = w*16 + gid;
        unsigned* Qu = (unsigned*)Qstage;
        unsigned* qfw = Qf + w*1024;
        #pragma unroll
        for (int j=0;j<8;j++){
            qfw[(j*4+0)*32 + lane] = Qu[r0*APAD + 8*j+tig];
            qfw[(j*4+1)*32 + lane] = Qu[(r0+8)*APAD + 8*j+tig];
            qfw[(j*4+2)*32 + lane] = Qu[r0*APAD + 8*j+tig+4];
            qfw[(j*4+3)*32 + lane] = Qu[(r0+8)*APAD + 8*j+tig+4];
        }
        __syncthreads();   // all warps done reading Qstage
    }
    int r0 = w*16 + gid;

    auto issue_kv = [&](int kt, int st){
        const float* kp = kbase + (size_t)(kt<<6)*DK;
        const float* vp = vbase + (size_t)(kt<<6)*DK;
        unsigned* Kst = KV + st*2*64*APAD;
        unsigned* Vst = Kst + 64*APAD;
        #pragma unroll
        for (int i=0;i<4;i++){
            int idx=tid+i*256, r=idx>>4, c=(idx&15)*4;
            cp16(&Kst[r*APAD+c], kp + (size_t)r*DK + c);
            cp16(&Vst[r*APAD+c], vp + (size_t)r*DK + c);
        }
        CP_COMMIT();
    };
    issue_kv(0, 0);

    float oacc[8][4]={};
    float m0=-1e30f, m1=-1e30f, l0=0.f, l1=0.f;
    int qg0 = q0 + r0;
    const int* mrow0 = mask + ((size_t)b*SEQ + qg0)*SEQ;
    const int* mrow1 = mrow0 + 8*SEQ;
    int srcA = (lane & ~3) | (tig>>1);
    int srcB = srcA + 2;
    float rb_lo = s_rb[0];   // rel <= -32
    float rb_hi = s_rb[64];  // rel >= 32
    const unsigned* qfw = Qf + w*1024 + lane;

    #pragma unroll 1
    for (int kt=0; kt<SEQ/64; kt++){
        int k0 = kt<<6;
        CP_WAIT0();
        __syncthreads();
        if (kt+1 < SEQ/64) issue_kv(kt+1, (kt+1)&1);

        unsigned* Kst = KV + (kt&1)*2*64*APAD;
        unsigned* Vst = Kst + 64*APAD;

        // S = Q @ K^T : warp tile 16x64, Q fragments from Qf
        float sacc[8][4]={};
        #pragma unroll
        for (int j=0;j<8;j++){
            unsigned a0=qfw[(j*4+0)*32];
            unsigned a1=qfw[(j*4+1)*32];
            unsigned a2=qfw[(j*4+2)*32];
            unsigned a3=qfw[(j*4+3)*32];
            #pragma unroll
            for (int nt=0;nt<8;nt++){
                unsigned b0=Kst[(nt*8+gid)*APAD + 8*j+tig];
                unsigned b1=Kst[(nt*8+gid)*APAD + 8*j+tig+4];
                mma8(sacc[nt], a0,a1,a2,a3, b0,b1);
            }
        }

        // scale + bias + mask (mask loaded inline, transient regs)
        float mx0=-1e30f, mx1=-1e30f;
        int dlo = qg0 - (k0+63);
        int dhi = qg0 + 15 - k0;
        if (dlo >= 32 || dhi <= -32) {
            float bc = (dlo >= 32) ? rb_hi : rb_lo;
            #pragma unroll
            for (int nt=0;nt<8;nt++){
                int c = k0 + nt*8 + 2*tig;
                int2 mk0v=*(const int2*)&mrow0[c];
                int2 mk1v=*(const int2*)&mrow1[c];
                sacc[nt][0] = (mk0v.x==0) ? -3e9f : fmaf(sacc[nt][0],SCALE_L2,bc);
                sacc[nt][1] = (mk0v.y==0) ? -3e9f : fmaf(sacc[nt][1],SCALE_L2,bc);
                sacc[nt][2] = (mk1v.x==0) ? -3e9f : fmaf(sacc[nt][2],SCALE_L2,bc);
                sacc[nt][3] = (mk1v.y==0) ? -3e9f : fmaf(sacc[nt][3],SCALE_L2,bc);
                mx0=fmaxf(mx0,fmaxf(sacc[nt][0],sacc[nt][1]));
                mx1=fmaxf(mx1,fmaxf(sacc[nt][2],sacc[nt][3]));
            }
        } else {
            #pragma unroll
            for (int nt=0;nt<8;nt++){
                int c = k0 + nt*8 + 2*tig;
                int2 mk0v=*(const int2*)&mrow0[c];
                int2 mk1v=*(const int2*)&mrow1[c];
                int ra = qg0 - c;
                float b00=s_rb[min(max(ra  ,-32),32)+32];
                float b01=s_rb[min(max(ra-1,-32),32)+32];
                float b10=s_rb[min(max(ra+8,-32),32)+32];
                float b11=s_rb[min(max(ra+7,-32),32)+32];
                sacc[nt][0] = (mk0v.x==0) ? -3e9f : fmaf(sacc[nt][0],SCALE_L2,b00);
                sacc[nt][1] = (mk0v.y==0) ? -3e9f : fmaf(sacc[nt][1],SCALE_L2,b01);
                sacc[nt][2] = (mk1v.x==0) ? -3e9f : fmaf(sacc[nt][2],SCALE_L2,b10);
                sacc[nt][3] = (mk1v.y==0) ? -3e9f : fmaf(sacc[nt][3],SCALE_L2,b11);
                mx0=fmaxf(mx0,fmaxf(sacc[nt][0],sacc[nt][1]));
                mx1=fmaxf(mx1,fmaxf(sacc[nt][2],sacc[nt][3]));
            }
        }
        mx0=fmaxf(mx0,__shfl_xor_sync(0xffffffffu,mx0,1));
        mx0=fmaxf(mx0,__shfl_xor_sync(0xffffffffu,mx0,2));
        mx1=fmaxf(mx1,__shfl_xor_sync(0xffffffffu,mx1,1));
        mx1=fmaxf(mx1,__shfl_xor_sync(0xffffffffu,mx1,2));
        float mn0=fmaxf(m0,mx0), mn1=fmaxf(m1,mx1);
        float fr0=fexp2(m0-mn0), fr1=fexp2(m1-mn1);
        m0=mn0; m1=mn1;
        float ps0=0.f, ps1=0.f;
        unsigned (*pu)[4] = (unsigned(*)[4])sacc;
        #pragma unroll
        for (int nt=0;nt<8;nt++){
            float p0=fexp2(sacc[nt][0]-mn0);
            float p1=fexp2(sacc[nt][1]-mn0);
            float p2=fexp2(sacc[nt][2]-mn1);
            float p3=fexp2(sacc[nt][3]-mn1);
            ps0 += p0+p1; ps1 += p2+p3;
            oacc[nt][0]*=fr0; oacc[nt][1]*=fr0; oacc[nt][2]*=fr1; oacc[nt][3]*=fr1;
            pu[nt][0]=f2tf(p0); pu[nt][1]=f2tf(p1); pu[nt][2]=f2tf(p2); pu[nt][3]=f2tf(p3);
        }
        ps0 += __shfl_xor_sync(0xffffffffu,ps0,1);
        ps0 += __shfl_xor_sync(0xffffffffu,ps0,2);
        ps1 += __shfl_xor_sync(0xffffffffu,ps1,1);
        ps1 += __shfl_xor_sync(0xffffffffu,ps1,2);
        l0 = l0*fr0 + ps0; l1 = l1*fr1 + ps1;

        // O += P @ V : P permuted acc->A-frag layout via intra-group shfl
        #pragma unroll
        for (int j=0;j<8;j++){
            unsigned sA0=__shfl_sync(0xffffffffu,pu[j][0],srcA);
            unsigned sA1=__shfl_sync(0xffffffffu,pu[j][1],srcA);
            unsigned sA2=__shfl_sync(0xffffffffu,pu[j][2],srcA);
            unsigned sA3=__shfl_sync(0xffffffffu,pu[j][3],srcA);
            unsigned sB0=__shfl_sync(0xffffffffu,pu[j][0],srcB);
            unsigned sB1=__shfl_sync(0xffffffffu,pu[j][1],srcB);
            unsigned sB2=__shfl_sync(0xffffffffu,pu[j][2],srcB);
            unsigned sB3=__shfl_sync(0xffffffffu,pu[j][3],srcB);
            bool hi = (tig & 1);
            unsigned a0 = hi? sA1 : sA0;
            unsigned a1 = hi? sA3 : sA2;
            unsigned a2 = hi? sB1 : sB0;
            unsigned a3 = hi? sB3 : sB2;
            #pragma unroll
            for (int nt=0;nt<8;nt++){
                unsigned b0=Vst[(8*j+tig)*APAD + nt*8+gid];
                unsigned b1=Vst[(8*j+tig+4)*APAD + nt*8+gid];
                mma8(oacc[nt], a0,a1,a2,a3, b0,b1);
            }
        }
    }

    float il0=1.f/l0, il1=1.f/l1;
    float* op = g_att + ((size_t)b*SEQ + qg0)*DM + h*64;
    #pragma unroll
    for (int nt=0;nt<8;nt++){
        int d=nt*8+2*tig;
        *(float2*)&op[d] = make_float2(
            __uint_as_float(f2tf(oacc[nt][0]*il0)),
            __uint_as_float(f2tf(oacc[nt][1]*il0)));
        *(float2*)&op[(size_t)8*DM + d] = make_float2(
            __uint_as_float(f2tf(oacc[nt][2]*il1)),
            __uint_as_float(f2tf(oacc[nt][3]*il1)));
    }
}

// ---------------------------------------------------------------------------
extern "C" void kernel_launch(void* const* d_in, const int* in_sizes, int n_in,
                              void* d_out, int out_size)
{
    const float* query = (const float*)d_in[0];
    const float* key   = (const float*)d_in[1];
    const float* value = (const float*)d_in[2];
    const int*   mask  = (const int*)  d_in[3];
    const float* Wq    = (const float*)d_in[4];
    const float* bq    = (const float*)d_in[5];
    const float* Wk    = (const float*)d_in[6];
    const float* bk    = (const float*)d_in[7];
    const float* Wv    = (const float*)d_in[8];
    const float* bv    = (const float*)d_in[9];
    const float* Wo    = (const float*)d_in[10];
    const float* bo    = (const float*)d_in[11];
    const float* rel   = (const float*)d_in[12];
    float* out = (float*)d_out;

    size_t gsmem = (size_t)(2*GBM*GPAD + 2*GBN*GPAD) * 4;       // 55296 B
    size_t asmem = (size_t)(4*64*APAD + 8192 + 68) * 4;         // 102672 B
    cudaFuncSetAttribute(gemm_qkv_kernel, cudaFuncAttributeMaxDynamicSharedMemorySize, (int)gsmem);
    cudaFuncSetAttribute(gemm_out_kernel, cudaFuncAttributeMaxDynamicSharedMemorySize, (int)gsmem);
    cudaFuncSetAttribute(attn_kernel, cudaFuncAttributeMaxDynamicSharedMemorySize, (int)asmem);

    relbias_kernel<<<1, 128>>>(rel);
    cvt_prepass<<<dim3(1024,1,7), 256>>>(query, key, value, Wq, Wk, Wv, Wo);

    dim3 pg(DM/GBN, NROW/GBM, 3);   // (16, 32, 3)
    gemm_qkv_kernel<<<pg, 256, gsmem>>>(bq, bk, bv);

    attn_kernel<<<dim3(SEQ/128, BATCH*H_), 256, asmem>>>(mask);

    gemm_out_kernel<<<dim3(DM/GBN, NROW/GBM), 256, gsmem>>>(bo, out);
}

// round 7
// speedup vs baseline: 3.1548x; 1.0931x over previous
#include <cuda_runtime.h>

#define H_    16
#define DM    1024
#define DK    64
#define BATCH 2
#define SEQ   2048
#define NROW  (BATCH*SEQ)   // 4096
#define NREL  65
#define LOG2E 1.4426950408889634f
#define SCALE_L2 (0.125f*LOG2E)

// Scratch (device globals: allocation-free scratch per harness rules)
__device__ float g_q[(size_t)BATCH*H_*SEQ*DK];     // natural [bh][s][d]
__device__ float g_k[(size_t)BATCH*H_*SEQ*DK];     // d-axis pair-interleaved
__device__ float g_vt[(size_t)BATCH*H_*DK*SEQ];    // [bh][d][s], s pair-interleaved
__device__ float g_att[(size_t)NROW*DM];           // d-axis pair-interleaved
__device__ float g_rb[NREL];
// tf32-pre-rounded copies, k-axis pair-interleaved for LDS.64 fragments
__device__ float g_cq[(size_t)NROW*DM];
__device__ float g_ck[(size_t)NROW*DM];
__device__ float g_cv[(size_t)NROW*DM];
__device__ float g_cwq[(size_t)DM*DM];
__device__ float g_cwk[(size_t)DM*DM];
__device__ float g_cwv[(size_t)DM*DM];
__device__ float g_cwo[(size_t)DM*DM];

// pair-interleave within 8-groups: true offset o stored at pos 2*(o&3)+(o>>2);
// LDS.64 at pos 2t then yields true (t, t+4) = one mma fragment pair.
__device__ __forceinline__ int ilv8(int o){ return ((o&3)<<1) | (o>>2); }

// ---------------------------------------------------------------------------
// helpers
// ---------------------------------------------------------------------------
__device__ __forceinline__ unsigned f2tf(float x){
    unsigned r; asm("cvt.rna.tf32.f32 %0, %1;" : "=r"(r) : "f"(x)); return r;
}
__device__ __forceinline__ void mma8(float d[4],
    unsigned a0,unsigned a1,unsigned a2,unsigned a3, unsigned b0,unsigned b1){
    asm volatile("mma.sync.aligned.m16n8k8.row.col.f32.tf32.tf32.f32 "
        "{%0,%1,%2,%3}, {%4,%5,%6,%7}, {%8,%9}, {%0,%1,%2,%3};"
        : "+f"(d[0]),"+f"(d[1]),"+f"(d[2]),"+f"(d[3])
        : "r"(a0),"r"(a1),"r"(a2),"r"(a3),"r"(b0),"r"(b1));
}
__device__ __forceinline__ void cp16(void* sp, const void* gp){
    unsigned s = (unsigned)__cvta_generic_to_shared(sp);
    asm volatile("cp.async.ca.shared.global [%0], [%1], 16;" :: "r"(s), "l"(gp));
}
#define CP_COMMIT() asm volatile("cp.async.commit_group;")
#define CP_WAIT0()  asm volatile("cp.async.wait_group 0;")
#define CP_WAIT1()  asm volatile("cp.async.wait_group 1;")

// exp2 on the fma/alu pipes (MUFU is only 0.5/cyc/SM on sm_103a)
__device__ __forceinline__ float fexp2(float y){
    y = fmaxf(y, -126.f);
    float z = y + 12582912.f;
    int   e = __float_as_int(z) - 0x4B400000;
    float f = y - (z - 12582912.f);
    float p =             1.3333558146e-3f;
    p = fmaf(p, f, 9.6181291918e-3f);
    p = fmaf(p, f, 5.5504108664e-2f);
    p = fmaf(p, f, 2.4022650695e-1f);
    p = fmaf(p, f, 6.9314718056e-1f);
    p = fmaf(p, f, 1.0f);
    return __int_as_float(__float_as_int(p) + (e << 23));
}

// ---------------------------------------------------------------------------
// prepass: tf32-round + k-axis pair-interleave (z selects array)
// ---------------------------------------------------------------------------
__global__ void cvt_prepass(const float* __restrict__ q, const float* __restrict__ k,
                            const float* __restrict__ v, const float* __restrict__ wq,
                            const float* __restrict__ wk, const float* __restrict__ wv,
                            const float* __restrict__ wo)
{
    int z = blockIdx.z;
    const float4* src; float* dst; int n4;
    switch (z) {
        case 0: src=(const float4*)q;  dst=g_cq;  n4=NROW*DM/4; break;
        case 1: src=(const float4*)k;  dst=g_ck;  n4=NROW*DM/4; break;
        case 2: src=(const float4*)v;  dst=g_cv;  n4=NROW*DM/4; break;
        case 3: src=(const float4*)wq; dst=g_cwq; n4=DM*DM/4;   break;
        case 4: src=(const float4*)wk; dst=g_cwk; n4=DM*DM/4;   break;
        case 5: src=(const float4*)wv; dst=g_cwv; n4=DM*DM/4;   break;
        default:src=(const float4*)wo; dst=g_cwo; n4=DM*DM/4;   break;
    }
    for (int i = blockIdx.x*blockDim.x + threadIdx.x; i < n4; i += gridDim.x*blockDim.x){
        float4 a = src[i];
        int par  = (i & 1);                       // true offsets 0-3 (even) / 4-7 (odd)
        size_t fb = ((size_t)i << 2) & ~7ull;     // 8-aligned flat base
        dst[fb + par + 0] = __uint_as_float(f2tf(a.x));
        dst[fb + par + 2] = __uint_as_float(f2tf(a.y));
        dst[fb + par + 4] = __uint_as_float(f2tf(a.z));
        dst[fb + par + 6] = __uint_as_float(f2tf(a.w));
    }
}

// ---------------------------------------------------------------------------
// rel bias (pre-scaled into log2 domain)
// ---------------------------------------------------------------------------
__global__ void relbias_kernel(const float* __restrict__ rel_emb) {
    int i = threadIdx.x;
    if (i < NREL) {
        float s = 0.f;
        #pragma unroll
        for (int d = 0; d < DK; d++) s += rel_emb[i*DK + d];
        g_rb[i] = s * LOG2E;
    }
}

// ---------------------------------------------------------------------------
// GEMM core: 3-stage cp.async, LDS.64 fragment loads (interleaved k storage).
// BM=128, BN=64, BK=32, 256 threads.
// MODE: 0 = scatter natural (g_q), 1 = scatter d-interleaved (g_k),
//       2 = scatter V-transposed into g_vt, 3 = plain row-major out.
// ---------------------------------------------------------------------------
#define GBM 128
#define GBN 64
#define GBK 32
#define GPAD 40
#define GNT  (DM/GBK)

template<int MODE>
__device__ __forceinline__ void gemm_core(const float* __restrict__ X,
    const float* __restrict__ W, const float* __restrict__ bias,
    float* __restrict__ dst)
{
    extern __shared__ unsigned gsm[];
    unsigned* As = gsm;                    // [3][128][GPAD]
    unsigned* Bs = gsm + 3*GBM*GPAD;       // [3][64][GPAD]

    int tid=threadIdx.x, lane=tid&31, w=tid>>5;
    int gid=lane>>2, tig=lane&3, wm=w>>1, wn=w&1;
    int m0=blockIdx.y*GBM, n0=blockIdx.x*GBN;

    int lr=tid>>3, lc=(tid&7)*4;
    const float* xp = X + (size_t)(m0+lr)*DM + lc;
    const float* wp = W + (size_t)(n0+lr)*DM + lc;

    auto issue = [&](int t, int buf){
        int k0 = t*GBK;
        #pragma unroll
        for (int i=0;i<4;i++)
            cp16(&As[buf*GBM*GPAD + (lr+32*i)*GPAD + lc], xp + k0 + (size_t)32*i*DM);
        #pragma unroll
        for (int i=0;i<2;i++)
            cp16(&Bs[buf*GBN*GPAD + (lr+32*i)*GPAD + lc], wp + k0 + (size_t)32*i*DM);
        CP_COMMIT();
    };

    issue(0, 0);
    issue(1, 1);

    float acc[2][4][4]={};
    int buf = 0;
    #pragma unroll 1
    for (int t=0;t<GNT;t++){
        if (t < GNT-1) { CP_WAIT1(); } else { CP_WAIT0(); }
        __syncthreads();
        if (t+2 < GNT) { int nb = buf+2; if (nb>=3) nb-=3; issue(t+2, nb); }

        unsigned* Ab = As + buf*GBM*GPAD;
        unsigned* Bb = Bs + buf*GBN*GPAD;
        #pragma unroll
        for (int kk=0;kk<4;kk++){
            int kc=kk*8 + 2*tig;
            unsigned af[2][4], bf[4][2];
            #pragma unroll
            for (int mi=0;mi<2;mi++){
                int r=wm*32+mi*16+gid;
                uint2 a02 = *(const uint2*)&Ab[r*GPAD+kc];
                uint2 a13 = *(const uint2*)&Ab[(r+8)*GPAD+kc];
                af[mi][0]=a02.x; af[mi][1]=a13.x; af[mi][2]=a02.y; af[mi][3]=a13.y;
            }
            #pragma unroll
            for (int ni=0;ni<4;ni++){
                int r=wn*32+ni*8+gid;
                uint2 b01 = *(const uint2*)&Bb[r*GPAD+kc];
                bf[ni][0]=b01.x; bf[ni][1]=b01.y;
            }
            #pragma unroll
            for (int mi=0;mi<2;mi++)
                #pragma unroll
                for (int ni=0;ni<4;ni++)
                    mma8(acc[mi][ni], af[mi][0],af[mi][1],af[mi][2],af[mi][3],
                         bf[ni][0],bf[ni][1]);
        }
        buf++; if (buf>=3) buf=0;
    }

    #pragma unroll
    for (int mi=0;mi<2;mi++){
        #pragma unroll
        for (int ni=0;ni<4;ni++){
            int row = m0 + wm*32 + mi*16 + gid;
            int col = n0 + wn*32 + ni*8 + 2*tig;
            float bv0 = bias[col], bv1 = bias[col+1];
            float y0 = acc[mi][ni][0]+bv0, y1 = acc[mi][ni][1]+bv1;
            float y2 = acc[mi][ni][2]+bv0, y3 = acc[mi][ni][3]+bv1;
            if (MODE==3){
                *(float2*)&dst[(size_t)row*DM + col]     = make_float2(y0,y1);
                *(float2*)&dst[(size_t)(row+8)*DM + col] = make_float2(y2,y3);
            } else {
                float r0f = __uint_as_float(f2tf(y0)), r1f = __uint_as_float(f2tf(y1));
                float r2f = __uint_as_float(f2tf(y2)), r3f = __uint_as_float(f2tf(y3));
                int hh = col >> 6, dk = col & 63;
                int b1_ = row >> 11, s1 = row & (SEQ-1);
                int r2 = row + 8;
                int b2_ = r2 >> 11, s2 = r2 & (SEQ-1);
                if (MODE==2){
                    // V: write transposed [bh][d][s-interleaved]
                    int sI1 = (s1 & ~7) | ilv8(s1 & 7);
                    int sI2 = (s2 & ~7) | ilv8(s2 & 7);
                    float* pd0 = &dst[(((size_t)b1_*H_ + hh)*DK + dk)*SEQ];
                    float* pd1 = &dst[(((size_t)b1_*H_ + hh)*DK + dk+1)*SEQ];
                    float* pe0 = &dst[(((size_t)b2_*H_ + hh)*DK + dk)*SEQ];
                    float* pe1 = &dst[(((size_t)b2_*H_ + hh)*DK + dk+1)*SEQ];
                    pd0[sI1]=r0f; pd1[sI1]=r1f; pe0[sI2]=r2f; pe1[sI2]=r3f;
                } else {
                    float* p1 = &dst[(((size_t)b1_*H_ + hh)*SEQ + s1)*DK];
                    float* p2 = &dst[(((size_t)b2_*H_ + hh)*SEQ + s2)*DK];
                    if (MODE==1){
                        int g = dk & ~7, o = dk & 7;
                        int c0 = g | ilv8(o), c1 = g | ilv8(o+1);
                        p1[c0]=r0f; p1[c1]=r1f; p2[c0]=r2f; p2[c1]=r3f;
                    } else {
                        *(float2*)&p1[dk] = make_float2(r0f, r1f);
                        *(float2*)&p2[dk] = make_float2(r2f, r3f);
                    }
                }
            }
        }
    }
}

__global__ void __launch_bounds__(256) gemm_qkv_kernel(
    const float* __restrict__ bq, const float* __restrict__ bk, const float* __restrict__ bv)
{
    int m = blockIdx.z;
    if (m==0)      gemm_core<0>(g_cq, g_cwq, bq, g_q);
    else if (m==1) gemm_core<1>(g_ck, g_cwk, bk, g_k);    // K: d-interleaved
    else           gemm_core<2>(g_cv, g_cwv, bv, g_vt);   // V: transposed
}

__global__ void __launch_bounds__(256) gemm_out_kernel(
    const float* __restrict__ bo, float* __restrict__ out)
{
    gemm_core<3>(g_att, g_cwo, bo, out);
}

// ---------------------------------------------------------------------------
// Flash attention: BQ=128, 8 warps x (16q x 64k). LDS.64/128 fragment loads,
// cp.async double-buffered K/V(transposed), register softmax, 2 CTAs/SM.
// ---------------------------------------------------------------------------
#define APAD 72

__global__ void __launch_bounds__(256, 2) attn_kernel(const int* __restrict__ mask)
{
    extern __shared__ unsigned sm_[];
    unsigned* KV = sm_;                    // [2 stages][K(64*APAD) V(64*APAD)]
    unsigned* Qf = sm_ + 4*64*APAD;        // [8 warps][8j][32 lanes][4] = 8192
    float* Qstage = (float*)sm_;           // overlay [128][APAD] over stage 0
    float* s_rb = (float*)(Qf + 8192);     // 72

    int tid=threadIdx.x, lane=tid&31, w=tid>>5;
    int gid=lane>>2, tig=lane&3;
    int bh=blockIdx.y, b=bh>>4, h=bh&15;
    int q0=blockIdx.x<<7;

    if (tid < NREL) s_rb[tid] = g_rb[tid];

    const float* kbase  = g_k  + (size_t)bh*SEQ*DK;
    const float* vtbase = g_vt + (size_t)bh*DK*SEQ;

    // stage Q, repack per-warp fragments into Qf[j][lane][4] (LDS.128 reload)
    {
        const float* qp = g_q + ((size_t)bh*SEQ + q0)*DK;
        #pragma unroll
        for (int i=0;i<8;i++){
            int idx=tid+i*256, r=idx>>4, c=(idx&15)*4;
            cp16(&Qstage[r*APAD+c], qp + (size_t)r*DK + c);
        }
        CP_COMMIT();
        CP_WAIT0();
        __syncthreads();
        int r0 = w*16 + gid;
        unsigned* Qu = (unsigned*)Qstage;
        unsigned* qfw = Qf + w*1024;
        #pragma unroll
        for (int j=0;j<8;j++){
            qfw[j*128 + lane*4 + 0] = Qu[r0*APAD + 8*j+tig];
            qfw[j*128 + lane*4 + 1] = Qu[(r0+8)*APAD + 8*j+tig];
            qfw[j*128 + lane*4 + 2] = Qu[r0*APAD + 8*j+tig+4];
            qfw[j*128 + lane*4 + 3] = Qu[(r0+8)*APAD + 8*j+tig+4];
        }
        __syncthreads();   // all warps done reading Qstage
    }
    int r0 = w*16 + gid;

    auto issue_kv = [&](int kt, int st){
        const float* kp = kbase  + (size_t)(kt<<6)*DK;   // K rows = keys (d interleaved)
        const float* vp = vtbase + (kt<<6);              // Vt rows = d (s interleaved)
        unsigned* Kst = KV + st*2*64*APAD;
        unsigned* Vst = Kst + 64*APAD;
        #pragma unroll
        for (int i=0;i<4;i++){
            int idx=tid+i*256, r=idx>>4, c=(idx&15)*4;
            cp16(&Kst[r*APAD+c], kp + (size_t)r*DK + c);
            cp16(&Vst[r*APAD+c], vp + (size_t)r*SEQ + c);
        }
        CP_COMMIT();
    };
    issue_kv(0, 0);

    float oacc[8][4]={};
    float m0=-1e30f, m1=-1e30f, l0=0.f, l1=0.f;
    int qg0 = q0 + r0;
    const int* mrow0 = mask + ((size_t)b*SEQ + qg0)*SEQ;
    const int* mrow1 = mrow0 + 8*SEQ;
    int srcA = (lane & ~3) | (tig>>1);
    int srcB = srcA + 2;
    float rb_lo = s_rb[0];   // rel <= -32
    float rb_hi = s_rb[64];  // rel >= 32
    const unsigned* qfw = Qf + w*1024 + lane*4;

    #pragma unroll 1
    for (int kt=0; kt<SEQ/64; kt++){
        int k0 = kt<<6;
        CP_WAIT0();
        __syncthreads();
        if (kt+1 < SEQ/64) issue_kv(kt+1, (kt+1)&1);

        unsigned* Kst = KV + (kt&1)*2*64*APAD;
        unsigned* Vst = Kst + 64*APAD;

        // S = Q @ K^T : Q frag LDS.128, K frag LDS.64 (interleaved d)
        float sacc[8][4]={};
        #pragma unroll
        for (int j=0;j<8;j++){
            uint4 qa = *(const uint4*)&qfw[j*128];
            #pragma unroll
            for (int nt=0;nt<8;nt++){
                uint2 kk2 = *(const uint2*)&Kst[(nt*8+gid)*APAD + 8*j + 2*tig];
                mma8(sacc[nt], qa.x,qa.y,qa.z,qa.w, kk2.x,kk2.y);
            }
        }

        // scale + bias + mask
        float mx0=-1e30f, mx1=-1e30f;
        int dlo = qg0 - (k0+63);
        int dhi = qg0 + 15 - k0;
        if (dlo >= 32 || dhi <= -32) {
            float bc = (dlo >= 32) ? rb_hi : rb_lo;
            #pragma unroll
            for (int nt=0;nt<8;nt++){
                int c = k0 + nt*8 + 2*tig;
                int2 mk0v=*(const int2*)&mrow0[c];
                int2 mk1v=*(const int2*)&mrow1[c];
                sacc[nt][0] = (mk0v.x==0) ? -3e9f : fmaf(sacc[nt][0],SCALE_L2,bc);
                sacc[nt][1] = (mk0v.y==0) ? -3e9f : fmaf(sacc[nt][1],SCALE_L2,bc);
                sacc[nt][2] = (mk1v.x==0) ? -3e9f : fmaf(sacc[nt][2],SCALE_L2,bc);
                sacc[nt][3] = (mk1v.y==0) ? -3e9f : fmaf(sacc[nt][3],SCALE_L2,bc);
                mx0=fmaxf(mx0,fmaxf(sacc[nt][0],sacc[nt][1]));
                mx1=fmaxf(mx1,fmaxf(sacc[nt][2],sacc[nt][3]));
            }
        } else {
            #pragma unroll
            for (int nt=0;nt<8;nt++){
                int c = k0 + nt*8 + 2*tig;
                int2 mk0v=*(const int2*)&mrow0[c];
                int2 mk1v=*(const int2*)&mrow1[c];
                int ra = qg0 - c;
                float b00=s_rb[min(max(ra  ,-32),32)+32];
                float b01=s_rb[min(max(ra-1,-32),32)+32];
                float b10=s_rb[min(max(ra+8,-32),32)+32];
                float b11=s_rb[min(max(ra+7,-32),32)+32];
                sacc[nt][0] = (mk0v.x==0) ? -3e9f : fmaf(sacc[nt][0],SCALE_L2,b00);
                sacc[nt][1] = (mk0v.y==0) ? -3e9f : fmaf(sacc[nt][1],SCALE_L2,b01);
                sacc[nt][2] = (mk1v.x==0) ? -3e9f : fmaf(sacc[nt][2],SCALE_L2,b10);
                sacc[nt][3] = (mk1v.y==0) ? -3e9f : fmaf(sacc[nt][3],SCALE_L2,b11);
                mx0=fmaxf(mx0,fmaxf(sacc[nt][0],sacc[nt][1]));
                mx1=fmaxf(mx1,fmaxf(sacc[nt][2],sacc[nt][3]));
            }
        }
        mx0=fmaxf(mx0,__shfl_xor_sync(0xffffffffu,mx0,1));
        mx0=fmaxf(mx0,__shfl_xor_sync(0xffffffffu,mx0,2));
        mx1=fmaxf(mx1,__shfl_xor_sync(0xffffffffu,mx1,1));
        mx1=fmaxf(mx1,__shfl_xor_sync(0xffffffffu,mx1,2));
        float mn0=fmaxf(m0,mx0), mn1=fmaxf(m1,mx1);
        float fr0=fexp2(m0-mn0), fr1=fexp2(m1-mn1);
        m0=mn0; m1=mn1;
        float ps0=0.f, ps1=0.f;
        unsigned (*pu)[4] = (unsigned(*)[4])sacc;
        #pragma unroll
        for (int nt=0;nt<8;nt++){
            float p0=fexp2(sacc[nt][0]-mn0);
            float p1=fexp2(sacc[nt][1]-mn0);
            float p2=fexp2(sacc[nt][2]-mn1);
            float p3=fexp2(sacc[nt][3]-mn1);
            ps0 += p0+p1; ps1 += p2+p3;
            oacc[nt][0]*=fr0; oacc[nt][1]*=fr0; oacc[nt][2]*=fr1; oacc[nt][3]*=fr1;
            pu[nt][0]=f2tf(p0); pu[nt][1]=f2tf(p1); pu[nt][2]=f2tf(p2); pu[nt][3]=f2tf(p3);
        }
        ps0 += __shfl_xor_sync(0xffffffffu,ps0,1);
        ps0 += __shfl_xor_sync(0xffffffffu,ps0,2);
        ps1 += __shfl_xor_sync(0xffffffffu,ps1,1);
        ps1 += __shfl_xor_sync(0xffffffffu,ps1,2);
        l0 = l0*fr0 + ps0; l1 = l1*fr1 + ps1;

        // O += P @ V : P via shfl permute, V frag LDS.64 (Vt rows = d)
        #pragma unroll
        for (int j=0;j<8;j++){
            unsigned sA0=__shfl_sync(0xffffffffu,pu[j][0],srcA);
            unsigned sA1=__shfl_sync(0xffffffffu,pu[j][1],srcA);
            unsigned sA2=__shfl_sync(0xffffffffu,pu[j][2],srcA);
            unsigned sA3=__shfl_sync(0xffffffffu,pu[j][3],srcA);
            unsigned sB0=__shfl_sync(0xffffffffu,pu[j][0],srcB);
            unsigned sB1=__shfl_sync(0xffffffffu,pu[j][1],srcB);
            unsigned sB2=__shfl_sync(0xffffffffu,pu[j][2],srcB);
            unsigned sB3=__shfl_sync(0xffffffffu,pu[j][3],srcB);
            bool hi = (tig & 1);
            unsigned a0 = hi? sA1 : sA0;
            unsigned a1 = hi? sA3 : sA2;
            unsigned a2 = hi? sB1 : sB0;
            unsigned a3 = hi? sB3 : sB2;
            #pragma unroll
            for (int nt=0;nt<8;nt++){
                uint2 vv2 = *(const uint2*)&Vst[(nt*8+gid)*APAD + 8*j + 2*tig];
                mma8(oacc[nt], a0,a1,a2,a3, vv2.x,vv2.y);
            }
        }
    }

    // normalize + write (d-interleaved for gemm_out's LDS.64 fragments)
    float il0=1.f/l0, il1=1.f/l1;
    float* op = g_att + ((size_t)b*SEQ + qg0)*DM + h*64;
    #pragma unroll
    for (int nt=0;nt<8;nt++){
        int d = nt*8 + 2*tig;
        int g = d & ~7, o = d & 7;
        int c0 = g | ilv8(o), c1 = g | ilv8(o+1);
        op[c0] = __uint_as_float(f2tf(oacc[nt][0]*il0));
        op[c1] = __uint_as_float(f2tf(oacc[nt][1]*il0));
        op[(size_t)8*DM + c0] = __uint_as_float(f2tf(oacc[nt][2]*il1));
        op[(size_t)8*DM + c1] = __uint_as_float(f2tf(oacc[nt][3]*il1));
    }
}

// ---------------------------------------------------------------------------
extern "C" void kernel_launch(void* const* d_in, const int* in_sizes, int n_in,
                              void* d_out, int out_size)
{
    const float* query = (const float*)d_in[0];
    const float* key   = (const float*)d_in[1];
    const float* value = (const float*)d_in[2];
    const int*   mask  = (const int*)  d_in[3];
    const float* Wq    = (const float*)d_in[4];
    const float* bq    = (const float*)d_in[5];
    const float* Wk    = (const float*)d_in[6];
    const float* bk    = (const float*)d_in[7];
    const float* Wv    = (const float*)d_in[8];
    const float* bv    = (const float*)d_in[9];
    const float* Wo    = (const float*)d_in[10];
    const float* bo    = (const float*)d_in[11];
    const float* rel   = (const float*)d_in[12];
    float* out = (float*)d_out;

    size_t gsmem = (size_t)(3*GBM*GPAD + 3*GBN*GPAD) * 4;       // 92160 B
    size_t asmem = (size_t)(4*64*APAD + 8192 + 72) * 4;         // 106784 B
    cudaFuncSetAttribute(gemm_qkv_kernel, cudaFuncAttributeMaxDynamicSharedMemorySize, (int)gsmem);
    cudaFuncSetAttribute(gemm_out_kernel, cudaFuncAttributeMaxDynamicSharedMemorySize, (int)gsmem);
    cudaFuncSetAttribute(attn_kernel, cudaFuncAttributeMaxDynamicSharedMemorySize, (int)asmem);

    relbias_kernel<<<1, 128>>>(rel);
    cvt_prepass<<<dim3(1024,1,7), 256>>>(query, key, value, Wq, Wk, Wv, Wo);

    dim3 pg(DM/GBN, NROW/GBM, 3);   // (16, 32, 3)
    gemm_qkv_kernel<<<pg, 256, gsmem>>>(bq, bk, bv);

    attn_kernel<<<dim3(SEQ/128, BATCH*H_), 256, asmem>>>(mask);

    gemm_out_kernel<<<dim3(DM/GBN, NROW/GBM), 256, gsmem>>>(bo, out);
}